// round 1
// baseline (speedup 1.0000x reference)
#include <cuda_runtime.h>
#include <math.h>
#include <stdint.h>

// ---------------- problem constants ----------------
#define Bq   4
#define Sq   2048
#define HIDq 1024
#define NHq  4
#define Dq   256          // head dim
#define IMq  2048
#define Eq   4
#define Tq   (Bq*Sq)      // 8192 tokens

// ---------------- scratch (device globals; no allocation allowed) --------
__device__ float g_X [Tq*HIDq];
__device__ float g_Q [Tq*HIDq];
__device__ float g_K [Tq*HIDq];
__device__ float g_V [Tq*HIDq];
__device__ float g_O [Tq*HIDq];
__device__ float g_H1[Tq*HIDq];
__device__ float g_X2[Tq*HIDq];
__device__ float g_S [67108864];     // 16 * 2048 * 2048 attention scores
__device__ float g_RW[Tq*Eq];
__device__ float g_G [Tq*IMq];
__device__ float g_GU[Tq*IMq];

// ---------------- block reductions ----------------
__device__ __forceinline__ float block_reduce_sum(float v, float* sh) {
    __syncthreads();
    int t = threadIdx.x, lane = t & 31, w = t >> 5;
    #pragma unroll
    for (int o = 16; o; o >>= 1) v += __shfl_down_sync(0xffffffffu, v, o);
    if (lane == 0) sh[w] = v;
    __syncthreads();
    float r = (t < (int)(blockDim.x >> 5)) ? sh[t] : 0.f;
    if (w == 0) {
        #pragma unroll
        for (int o = 16; o; o >>= 1) r += __shfl_down_sync(0xffffffffu, r, o);
        if (t == 0) sh[0] = r;
    }
    __syncthreads();
    return sh[0];
}

__device__ __forceinline__ float block_reduce_max(float v, float* sh) {
    __syncthreads();
    int t = threadIdx.x, lane = t & 31, w = t >> 5;
    #pragma unroll
    for (int o = 16; o; o >>= 1) v = fmaxf(v, __shfl_down_sync(0xffffffffu, v, o));
    if (lane == 0) sh[w] = v;
    __syncthreads();
    float r = (t < (int)(blockDim.x >> 5)) ? sh[t] : -1e30f;
    if (w == 0) {
        #pragma unroll
        for (int o = 16; o; o >>= 1) r = fmaxf(r, __shfl_down_sync(0xffffffffu, r, o));
        if (t == 0) sh[0] = r;
    }
    __syncthreads();
    return sh[0];
}

// ---------------- RMSNorm: one block (256 thr) per 1024-wide row ----------
__global__ void rms_k(const float* __restrict__ x, const float* __restrict__ w,
                      float* __restrict__ y) {
    __shared__ float sh[32];
    long long row = blockIdx.x;
    const float4 xv = *(const float4*)(x + row * HIDq + threadIdx.x * 4);
    float ss = xv.x*xv.x + xv.y*xv.y + xv.z*xv.z + xv.w*xv.w;
    ss = block_reduce_sum(ss, sh);
    float inv = rsqrtf(ss * (1.0f / (float)HIDq) + 1e-6f);
    const float4 wv = *(const float4*)(w + threadIdx.x * 4);
    float4 o;
    o.x = xv.x * inv * wv.x; o.y = xv.y * inv * wv.y;
    o.z = xv.z * inv * wv.z; o.w = xv.w * inv * wv.w;
    *(float4*)(y + row * HIDq + threadIdx.x * 4) = o;
}

// ---------------- row softmax over 2048 entries (one block per row) ------
__global__ void softmax_k(float* __restrict__ s) {
    __shared__ float sh[32];
    float* p = s + (long long)blockIdx.x * (long long)Sq;
    int t = threadIdx.x;
    float v[8];
    float mx = -1e30f;
    #pragma unroll
    for (int i = 0; i < 8; i++) { v[i] = p[t + 256 * i]; mx = fmaxf(mx, v[i]); }
    mx = block_reduce_max(mx, sh);
    float sum = 0.f;
    #pragma unroll
    for (int i = 0; i < 8; i++) { v[i] = expf(v[i] - mx); sum += v[i]; }
    sum = block_reduce_sum(sum, sh);
    float inv = 1.0f / sum;
    #pragma unroll
    for (int i = 0; i < 8; i++) p[t + 256 * i] = v[i] * inv;
}

// ---------------- router: 1 warp / token, N=4 experts ----------------
__global__ void router_k(const float* __restrict__ x2, const float* __restrict__ rwt,
                         const float* __restrict__ rb, float* __restrict__ rw) {
    int warp = threadIdx.x >> 5, lane = threadIdx.x & 31;
    long long token = (long long)blockIdx.x * (blockDim.x >> 5) + warp;
    const float* xr = x2 + token * HIDq;
    float a0 = 0.f, a1 = 0.f, a2 = 0.f, a3 = 0.f;
    for (int k = lane; k < HIDq; k += 32) {
        float xv = xr[k];
        float4 w4 = *(const float4*)(rwt + (long long)k * Eq);
        a0 = fmaf(xv, w4.x, a0); a1 = fmaf(xv, w4.y, a1);
        a2 = fmaf(xv, w4.z, a2); a3 = fmaf(xv, w4.w, a3);
    }
    #pragma unroll
    for (int o = 16; o; o >>= 1) {
        a0 += __shfl_down_sync(0xffffffffu, a0, o);
        a1 += __shfl_down_sync(0xffffffffu, a1, o);
        a2 += __shfl_down_sync(0xffffffffu, a2, o);
        a3 += __shfl_down_sync(0xffffffffu, a3, o);
    }
    if (lane == 0) {
        float l0 = a0 + rb[0], l1 = a1 + rb[1], l2 = a2 + rb[2], l3 = a3 + rb[3];
        float m = fmaxf(fmaxf(l0, l1), fmaxf(l2, l3));
        float e0 = expf(l0 - m), e1 = expf(l1 - m), e2 = expf(l2 - m), e3 = expf(l3 - m);
        float inv = 1.0f / (e0 + e1 + e2 + e3);
        float4 o; o.x = e0 * inv; o.y = e1 * inv; o.z = e2 * inv; o.w = e3 * inv;
        *(float4*)(rw + token * Eq) = o;
    }
}

// ---------------- balance loss: single block, deterministic --------------
__global__ void balance_k(const float* __restrict__ rw, float* __restrict__ out,
                          long long tail_begin, long long out_size) {
    __shared__ float red[1024];
    int t = threadIdx.x;
    float s = 0.f;
    for (int idx = t; idx < Sq * Eq; idx += 1024) {
        int srow = idx / Eq, e = idx % Eq;
        float m = 0.f;
        #pragma unroll
        for (int b = 0; b < Bq; b++)
            m += rw[((long long)b * Sq + srow) * Eq + e];
        m *= (1.0f / Bq);
        float d = m - 1.0f / (float)Eq;
        s += d * d;
    }
    red[t] = s;
    __syncthreads();
    for (int o = 512; o; o >>= 1) { if (t < o) red[t] += red[t + o]; __syncthreads(); }
    if (t == 0) {
        float loss = red[0] / ((float)Sq * (float)Eq) * 0.01f;
        for (long long i = tail_begin; i < out_size; i++) out[i] = loss;
    }
}

// ---------------- generic 128x128x16 SGEMM with fused epilogues ----------
enum { EPI_NONE = 0, EPI_ELU1, EPI_SILU, EPI_MUL, EPI_ADD, EPI_SCALEACC };

template<int EPI, bool TRANSB>
__global__ __launch_bounds__(256, 2)
void gemm_k(int M, int N, int K,
            const float* __restrict__ A, int lda, long long sAb, long long sAh,
            const float* __restrict__ B, int ldb, long long sBb, long long sBh,
            float*       C,              int ldc, long long sCb, long long sCh,
            const float* __restrict__ D,
            const float* __restrict__ scale, int sstride) {
    __shared__ float As[16][128];
    __shared__ float Bs[16][128];

    const int zb = blockIdx.z / NHq, zh = blockIdx.z % NHq;
    A += zb * sAb + zh * sAh;
    B += zb * sBb + zh * sBh;
    C += zb * sCb + zh * sCh;
    if (EPI == EPI_ADD || EPI == EPI_MUL) D += zb * sCb + zh * sCh;

    const int t = threadIdx.x;
    const int tx = t & 15, ty = t >> 4;
    const int row0 = blockIdx.y * 128;
    const int col0 = blockIdx.x * 128;

    float acc[8][8];
    #pragma unroll
    for (int i = 0; i < 8; i++)
        #pragma unroll
        for (int j = 0; j < 8; j++) acc[i][j] = 0.f;

    for (int k0 = 0; k0 < K; k0 += 16) {
        {   // A tile: 128 rows x 16 k, transposed into As[k][m]
            int ar = t >> 2;
            int ac = (t & 3) << 2;
            #pragma unroll
            for (int rr = 0; rr < 2; rr++) {
                int r = ar + rr * 64;
                const float4 v = *(const float4*)(A + (long long)(row0 + r) * lda + k0 + ac);
                As[ac + 0][r] = v.x; As[ac + 1][r] = v.y;
                As[ac + 2][r] = v.z; As[ac + 3][r] = v.w;
            }
        }
        if (!TRANSB) {  // B: K x N row-major
            int br = t >> 5;
            int bc = (t & 31) << 2;
            #pragma unroll
            for (int rr = 0; rr < 2; rr++) {
                int r = br + rr * 8;
                *(float4*)&Bs[r][bc] =
                    *(const float4*)(B + (long long)(k0 + r) * ldb + col0 + bc);
            }
        } else {        // B: N x K row-major (compute A * B^T)
            int br = t >> 2;
            int bc = (t & 3) << 2;
            #pragma unroll
            for (int rr = 0; rr < 2; rr++) {
                int r = br + rr * 64;
                const float4 v = *(const float4*)(B + (long long)(col0 + r) * ldb + k0 + bc);
                Bs[bc + 0][r] = v.x; Bs[bc + 1][r] = v.y;
                Bs[bc + 2][r] = v.z; Bs[bc + 3][r] = v.w;
            }
        }
        __syncthreads();
        #pragma unroll
        for (int k = 0; k < 16; k++) {
            float a[8], b[8];
            *(float4*)&a[0] = *(const float4*)&As[k][ty * 8];
            *(float4*)&a[4] = *(const float4*)&As[k][ty * 8 + 4];
            *(float4*)&b[0] = *(const float4*)&Bs[k][tx * 8];
            *(float4*)&b[4] = *(const float4*)&Bs[k][tx * 8 + 4];
            #pragma unroll
            for (int i = 0; i < 8; i++)
                #pragma unroll
                for (int j = 0; j < 8; j++)
                    acc[i][j] = fmaf(a[i], b[j], acc[i][j]);
        }
        __syncthreads();
    }

    // epilogue
    #pragma unroll
    for (int i = 0; i < 8; i++) {
        const long long row = row0 + ty * 8 + i;
        float sc = 0.f;
        if (EPI == EPI_SCALEACC) sc = __ldg(scale + row * sstride);
        #pragma unroll
        for (int j0 = 0; j0 < 8; j0 += 4) {
            const long long idx = row * ldc + col0 + tx * 8 + j0;
            float vv[4];
            #pragma unroll
            for (int j = 0; j < 4; j++) vv[j] = acc[i][j0 + j];
            if (EPI == EPI_ELU1) {
                #pragma unroll
                for (int j = 0; j < 4; j++)
                    vv[j] = (vv[j] >= 0.f) ? (vv[j] + 1.0f) : expf(vv[j]);
            } else if (EPI == EPI_SILU) {
                #pragma unroll
                for (int j = 0; j < 4; j++)
                    vv[j] = vv[j] / (1.0f + expf(-vv[j]));
            } else if (EPI == EPI_MUL) {
                float4 d4 = *(const float4*)(D + idx);
                vv[0] *= d4.x; vv[1] *= d4.y; vv[2] *= d4.z; vv[3] *= d4.w;
            } else if (EPI == EPI_ADD) {
                float4 d4 = *(const float4*)(D + idx);
                vv[0] += d4.x; vv[1] += d4.y; vv[2] += d4.z; vv[3] += d4.w;
            } else if (EPI == EPI_SCALEACC) {
                float4 c4 = *(const float4*)(C + idx);
                vv[0] = fmaf(vv[0], sc, c4.x); vv[1] = fmaf(vv[1], sc, c4.y);
                vv[2] = fmaf(vv[2], sc, c4.z); vv[3] = fmaf(vv[3], sc, c4.w);
            }
            float4 r; r.x = vv[0]; r.y = vv[1]; r.z = vv[2]; r.w = vv[3];
            *(float4*)(C + idx) = r;
        }
    }
}

// ---------------- host side ----------------
extern "C" void kernel_launch(void* const* d_in, const int* in_sizes, int n_in,
                              void* d_out, int out_size) {
    const float* hidden = (const float*)d_in[0];
    const float* ln1    = (const float*)d_in[1];
    const float* wq     = (const float*)d_in[2];
    const float* wk     = (const float*)d_in[3];
    const float* wv     = (const float*)d_in[4];
    const float* wo     = (const float*)d_in[5];
    const float* ln2    = (const float*)d_in[6];
    const float* rwt    = (const float*)d_in[7];
    const float* rb     = (const float*)d_in[8];
    const float* gw     = (const float*)d_in[9];
    const float* uw     = (const float*)d_in[10];
    const float* dw     = (const float*)d_in[11];
    float* out = (float*)d_out;

    float *pX, *pQ, *pK, *pV, *pO, *pH1, *pX2, *pS, *pRW, *pG, *pGU;
    cudaGetSymbolAddress((void**)&pX,  g_X);
    cudaGetSymbolAddress((void**)&pQ,  g_Q);
    cudaGetSymbolAddress((void**)&pK,  g_K);
    cudaGetSymbolAddress((void**)&pV,  g_V);
    cudaGetSymbolAddress((void**)&pO,  g_O);
    cudaGetSymbolAddress((void**)&pH1, g_H1);
    cudaGetSymbolAddress((void**)&pX2, g_X2);
    cudaGetSymbolAddress((void**)&pS,  g_S);
    cudaGetSymbolAddress((void**)&pRW, g_RW);
    cudaGetSymbolAddress((void**)&pG,  g_G);
    cudaGetSymbolAddress((void**)&pGU, g_GU);

    const dim3 blk(256);
    const long long ZERO = 0;

    // 1) x = rms(hidden, ln1)
    rms_k<<<Tq, 256>>>(hidden, ln1, pX);

    // 2) QKV projections (elu+1 fused for Q,K)
    dim3 g1(HIDq / 128, Tq / 128, 1);
    gemm_k<EPI_ELU1, false><<<g1, blk>>>(Tq, HIDq, HIDq,
        pX, HIDq, ZERO, ZERO, wq, HIDq, ZERO, ZERO, pQ, HIDq, ZERO, ZERO, nullptr, nullptr, 0);
    gemm_k<EPI_ELU1, false><<<g1, blk>>>(Tq, HIDq, HIDq,
        pX, HIDq, ZERO, ZERO, wk, HIDq, ZERO, ZERO, pK, HIDq, ZERO, ZERO, nullptr, nullptr, 0);
    gemm_k<EPI_NONE, false><<<g1, blk>>>(Tq, HIDq, HIDq,
        pX, HIDq, ZERO, ZERO, wv, HIDq, ZERO, ZERO, pV, HIDq, ZERO, ZERO, nullptr, nullptr, 0);

    // 3) scores = Q_head @ K_head^T  (batched over 16 (b,h) pairs)
    dim3 g2(Sq / 128, Sq / 128, Bq * NHq);
    gemm_k<EPI_NONE, true><<<g2, blk>>>(Sq, Sq, Dq,
        pQ, HIDq, (long long)Sq * HIDq, (long long)Dq,
        pK, HIDq, (long long)Sq * HIDq, (long long)Dq,
        pS, Sq,   (long long)NHq * Sq * Sq, (long long)Sq * Sq,
        nullptr, nullptr, 0);

    // 4) row softmax
    softmax_k<<<Bq * NHq * Sq, 256>>>(pS);

    // 5) O = attn @ V_head
    dim3 g3(Dq / 128, Sq / 128, Bq * NHq);
    gemm_k<EPI_NONE, false><<<g3, blk>>>(Sq, Dq, Sq,
        pS, Sq,   (long long)NHq * Sq * Sq, (long long)Sq * Sq,
        pV, HIDq, (long long)Sq * HIDq, (long long)Dq,
        pO, HIDq, (long long)Sq * HIDq, (long long)Dq,
        nullptr, nullptr, 0);

    // 6) h1 = hidden + O @ wo
    gemm_k<EPI_ADD, false><<<g1, blk>>>(Tq, HIDq, HIDq,
        pO, HIDq, ZERO, ZERO, wo, HIDq, ZERO, ZERO, pH1, HIDq, ZERO, ZERO, hidden, nullptr, 0);

    // 7) x2 = rms(h1, ln2)
    rms_k<<<Tq, 256>>>(pH1, ln2, pX2);

    // 8) router softmax weights
    router_k<<<Tq / 8, 256>>>(pX2, rwt, rb, pRW);

    // 9) balance loss -> tail of out (if present)
    balance_k<<<1, 1024>>>(pRW, out, (long long)Tq * HIDq, (long long)out_size);

    // 10) out[0 : T*HID) = h1
    cudaMemcpyAsync(out, pH1, (size_t)Tq * HIDq * sizeof(float),
                    cudaMemcpyDeviceToDevice);

    // 11) dense MoE: out += silu(x2@gate)*(x2@up) @ down * rw[:,e]
    dim3 g4(IMq / 128, Tq / 128, 1);
    dim3 g5(HIDq / 128, Tq / 128, 1);
    for (int e = 0; e < Eq; e++) {
        const float* ge = gw + (long long)e * HIDq * IMq;
        const float* ue = uw + (long long)e * HIDq * IMq;
        const float* de = dw + (long long)e * IMq * HIDq;
        gemm_k<EPI_SILU, false><<<g4, blk>>>(Tq, IMq, HIDq,
            pX2, HIDq, ZERO, ZERO, ge, IMq, ZERO, ZERO, pG, IMq, ZERO, ZERO, nullptr, nullptr, 0);
        gemm_k<EPI_MUL, false><<<g4, blk>>>(Tq, IMq, HIDq,
            pX2, HIDq, ZERO, ZERO, ue, IMq, ZERO, ZERO, pGU, IMq, ZERO, ZERO, pG, nullptr, 0);
        gemm_k<EPI_SCALEACC, false><<<g5, blk>>>(Tq, HIDq, IMq,
            pGU, IMq, ZERO, ZERO, de, HIDq, ZERO, ZERO, out, HIDq, ZERO, ZERO,
            nullptr, pRW + e, Eq);
    }
}

// round 2
// speedup vs baseline: 1.0000x; 1.0000x over previous
#include <cuda_runtime.h>
#include <math.h>
#include <stdint.h>

// ---------------- problem constants ----------------
#define Bq   4
#define Sq   2048
#define HIDq 1024
#define NHq  4
#define Dq   256          // head dim
#define IMq  2048
#define Eq   4
#define Tq   (Bq*Sq)      // 8192 tokens

// ---------------- scratch (device globals; no allocation allowed) --------
__device__ float g_X [Tq*HIDq];
__device__ float g_Q [Tq*HIDq];
__device__ float g_K [Tq*HIDq];
__device__ float g_V [Tq*HIDq];
__device__ float g_O [Tq*HIDq];
__device__ float g_H1[Tq*HIDq];
__device__ float g_X2[Tq*HIDq];
__device__ float g_S [67108864];     // 16 * 2048 * 2048 attention scores
__device__ float g_RW[Tq*Eq];
__device__ float g_G [Tq*IMq];
__device__ float g_GU[Tq*IMq];

// ---------------- block reductions ----------------
__device__ __forceinline__ float block_reduce_sum(float v, float* sh) {
    __syncthreads();
    int t = threadIdx.x, lane = t & 31, w = t >> 5;
    #pragma unroll
    for (int o = 16; o; o >>= 1) v += __shfl_down_sync(0xffffffffu, v, o);
    if (lane == 0) sh[w] = v;
    __syncthreads();
    float r = (t < (int)(blockDim.x >> 5)) ? sh[t] : 0.f;
    if (w == 0) {
        #pragma unroll
        for (int o = 16; o; o >>= 1) r += __shfl_down_sync(0xffffffffu, r, o);
        if (t == 0) sh[0] = r;
    }
    __syncthreads();
    return sh[0];
}

__device__ __forceinline__ float block_reduce_max(float v, float* sh) {
    __syncthreads();
    int t = threadIdx.x, lane = t & 31, w = t >> 5;
    #pragma unroll
    for (int o = 16; o; o >>= 1) v = fmaxf(v, __shfl_down_sync(0xffffffffu, v, o));
    if (lane == 0) sh[w] = v;
    __syncthreads();
    float r = (t < (int)(blockDim.x >> 5)) ? sh[t] : -1e30f;
    if (w == 0) {
        #pragma unroll
        for (int o = 16; o; o >>= 1) r = fmaxf(r, __shfl_down_sync(0xffffffffu, r, o));
        if (t == 0) sh[0] = r;
    }
    __syncthreads();
    return sh[0];
}

// ---------------- RMSNorm: one block (256 thr) per 1024-wide row ----------
__global__ void rms_k(const float* __restrict__ x, const float* __restrict__ w,
                      float* __restrict__ y) {
    __shared__ float sh[32];
    long long row = blockIdx.x;
    const float4 xv = *(const float4*)(x + row * HIDq + threadIdx.x * 4);
    float ss = xv.x*xv.x + xv.y*xv.y + xv.z*xv.z + xv.w*xv.w;
    ss = block_reduce_sum(ss, sh);
    float inv = rsqrtf(ss * (1.0f / (float)HIDq) + 1e-6f);
    const float4 wv = *(const float4*)(w + threadIdx.x * 4);
    float4 o;
    o.x = xv.x * inv * wv.x; o.y = xv.y * inv * wv.y;
    o.z = xv.z * inv * wv.z; o.w = xv.w * inv * wv.w;
    *(float4*)(y + row * HIDq + threadIdx.x * 4) = o;
}

// ---------------- row softmax over 2048 entries (one block per row) ------
__global__ void softmax_k(float* __restrict__ s) {
    __shared__ float sh[32];
    float* p = s + (long long)blockIdx.x * (long long)Sq;
    int t = threadIdx.x;
    float v[8];
    float mx = -1e30f;
    #pragma unroll
    for (int i = 0; i < 8; i++) { v[i] = p[t + 256 * i]; mx = fmaxf(mx, v[i]); }
    mx = block_reduce_max(mx, sh);
    float sum = 0.f;
    #pragma unroll
    for (int i = 0; i < 8; i++) { v[i] = expf(v[i] - mx); sum += v[i]; }
    sum = block_reduce_sum(sum, sh);
    float inv = 1.0f / sum;
    #pragma unroll
    for (int i = 0; i < 8; i++) p[t + 256 * i] = v[i] * inv;
}

// ---------------- router: 1 warp / token, N=4 experts ----------------
__global__ void router_k(const float* __restrict__ x2, const float* __restrict__ rwt,
                         const float* __restrict__ rb, float* __restrict__ rw) {
    int warp = threadIdx.x >> 5, lane = threadIdx.x & 31;
    long long token = (long long)blockIdx.x * (blockDim.x >> 5) + warp;
    const float* xr = x2 + token * HIDq;
    float a0 = 0.f, a1 = 0.f, a2 = 0.f, a3 = 0.f;
    for (int k = lane; k < HIDq; k += 32) {
        float xv = xr[k];
        float4 w4 = *(const float4*)(rwt + (long long)k * Eq);
        a0 = fmaf(xv, w4.x, a0); a1 = fmaf(xv, w4.y, a1);
        a2 = fmaf(xv, w4.z, a2); a3 = fmaf(xv, w4.w, a3);
    }
    #pragma unroll
    for (int o = 16; o; o >>= 1) {
        a0 += __shfl_down_sync(0xffffffffu, a0, o);
        a1 += __shfl_down_sync(0xffffffffu, a1, o);
        a2 += __shfl_down_sync(0xffffffffu, a2, o);
        a3 += __shfl_down_sync(0xffffffffu, a3, o);
    }
    if (lane == 0) {
        float l0 = a0 + rb[0], l1 = a1 + rb[1], l2 = a2 + rb[2], l3 = a3 + rb[3];
        float m = fmaxf(fmaxf(l0, l1), fmaxf(l2, l3));
        float e0 = expf(l0 - m), e1 = expf(l1 - m), e2 = expf(l2 - m), e3 = expf(l3 - m);
        float inv = 1.0f / (e0 + e1 + e2 + e3);
        float4 o; o.x = e0 * inv; o.y = e1 * inv; o.z = e2 * inv; o.w = e3 * inv;
        *(float4*)(rw + token * Eq) = o;
    }
}

// ---------------- balance loss: single block, deterministic --------------
__global__ void balance_k(const float* __restrict__ rw, float* __restrict__ out,
                          long long tail_begin, long long out_size) {
    __shared__ float red[1024];
    int t = threadIdx.x;
    float s = 0.f;
    for (int idx = t; idx < Sq * Eq; idx += 1024) {
        int srow = idx / Eq, e = idx % Eq;
        float m = 0.f;
        #pragma unroll
        for (int b = 0; b < Bq; b++)
            m += rw[((long long)b * Sq + srow) * Eq + e];
        m *= (1.0f / Bq);
        float d = m - 1.0f / (float)Eq;
        s += d * d;
    }
    red[t] = s;
    __syncthreads();
    for (int o = 512; o; o >>= 1) { if (t < o) red[t] += red[t + o]; __syncthreads(); }
    if (t == 0) {
        float loss = red[0] / ((float)Sq * (float)Eq) * 0.01f;
        for (long long i = tail_begin; i < out_size; i++) out[i] = loss;
    }
}

// ---------------- generic 128x128x16 SGEMM with fused epilogues ----------
enum { EPI_NONE = 0, EPI_ELU1, EPI_SILU, EPI_MUL, EPI_ADD, EPI_SCALEACC };

template<int EPI, bool TRANSB>
__global__ __launch_bounds__(256, 2)
void gemm_k(int M, int N, int K,
            const float* __restrict__ A, int lda, long long sAb, long long sAh,
            const float* __restrict__ B, int ldb, long long sBb, long long sBh,
            float*       C,              int ldc, long long sCb, long long sCh,
            const float* __restrict__ D,
            const float* __restrict__ scale, int sstride) {
    __shared__ float As[16][128];
    __shared__ float Bs[16][128];

    const int zb = blockIdx.z / NHq, zh = blockIdx.z % NHq;
    A += zb * sAb + zh * sAh;
    B += zb * sBb + zh * sBh;
    C += zb * sCb + zh * sCh;
    if (EPI == EPI_ADD || EPI == EPI_MUL) D += zb * sCb + zh * sCh;

    const int t = threadIdx.x;
    const int tx = t & 15, ty = t >> 4;
    const int row0 = blockIdx.y * 128;
    const int col0 = blockIdx.x * 128;

    float acc[8][8];
    #pragma unroll
    for (int i = 0; i < 8; i++)
        #pragma unroll
        for (int j = 0; j < 8; j++) acc[i][j] = 0.f;

    for (int k0 = 0; k0 < K; k0 += 16) {
        {   // A tile: 128 rows x 16 k, transposed into As[k][m]
            int ar = t >> 2;
            int ac = (t & 3) << 2;
            #pragma unroll
            for (int rr = 0; rr < 2; rr++) {
                int r = ar + rr * 64;
                const float4 v = *(const float4*)(A + (long long)(row0 + r) * lda + k0 + ac);
                As[ac + 0][r] = v.x; As[ac + 1][r] = v.y;
                As[ac + 2][r] = v.z; As[ac + 3][r] = v.w;
            }
        }
        if (!TRANSB) {  // B: K x N row-major
            int br = t >> 5;
            int bc = (t & 31) << 2;
            #pragma unroll
            for (int rr = 0; rr < 2; rr++) {
                int r = br + rr * 8;
                *(float4*)&Bs[r][bc] =
                    *(const float4*)(B + (long long)(k0 + r) * ldb + col0 + bc);
            }
        } else {        // B: N x K row-major (compute A * B^T)
            int br = t >> 2;
            int bc = (t & 3) << 2;
            #pragma unroll
            for (int rr = 0; rr < 2; rr++) {
                int r = br + rr * 64;
                const float4 v = *(const float4*)(B + (long long)(col0 + r) * ldb + k0 + bc);
                Bs[bc + 0][r] = v.x; Bs[bc + 1][r] = v.y;
                Bs[bc + 2][r] = v.z; Bs[bc + 3][r] = v.w;
            }
        }
        __syncthreads();
        #pragma unroll
        for (int k = 0; k < 16; k++) {
            float a[8], b[8];
            *(float4*)&a[0] = *(const float4*)&As[k][ty * 8];
            *(float4*)&a[4] = *(const float4*)&As[k][ty * 8 + 4];
            *(float4*)&b[0] = *(const float4*)&Bs[k][tx * 8];
            *(float4*)&b[4] = *(const float4*)&Bs[k][tx * 8 + 4];
            #pragma unroll
            for (int i = 0; i < 8; i++)
                #pragma unroll
                for (int j = 0; j < 8; j++)
                    acc[i][j] = fmaf(a[i], b[j], acc[i][j]);
        }
        __syncthreads();
    }

    // epilogue
    #pragma unroll
    for (int i = 0; i < 8; i++) {
        const long long row = row0 + ty * 8 + i;
        float sc = 0.f;
        if (EPI == EPI_SCALEACC) sc = __ldg(scale + row * sstride);
        #pragma unroll
        for (int j0 = 0; j0 < 8; j0 += 4) {
            const long long idx = row * ldc + col0 + tx * 8 + j0;
            float vv[4];
            #pragma unroll
            for (int j = 0; j < 4; j++) vv[j] = acc[i][j0 + j];
            if (EPI == EPI_ELU1) {
                #pragma unroll
                for (int j = 0; j < 4; j++)
                    vv[j] = (vv[j] >= 0.f) ? (vv[j] + 1.0f) : expf(vv[j]);
            } else if (EPI == EPI_SILU) {
                #pragma unroll
                for (int j = 0; j < 4; j++)
                    vv[j] = vv[j] / (1.0f + expf(-vv[j]));
            } else if (EPI == EPI_MUL) {
                float4 d4 = *(const float4*)(D + idx);
                vv[0] *= d4.x; vv[1] *= d4.y; vv[2] *= d4.z; vv[3] *= d4.w;
            } else if (EPI == EPI_ADD) {
                float4 d4 = *(const float4*)(D + idx);
                vv[0] += d4.x; vv[1] += d4.y; vv[2] += d4.z; vv[3] += d4.w;
            } else if (EPI == EPI_SCALEACC) {
                float4 c4 = *(const float4*)(C + idx);
                vv[0] = fmaf(vv[0], sc, c4.x); vv[1] = fmaf(vv[1], sc, c4.y);
                vv[2] = fmaf(vv[2], sc, c4.z); vv[3] = fmaf(vv[3], sc, c4.w);
            }
            float4 r; r.x = vv[0]; r.y = vv[1]; r.z = vv[2]; r.w = vv[3];
            *(float4*)(C + idx) = r;
        }
    }
}

// ---------------- host side ----------------
extern "C" void kernel_launch(void* const* d_in, const int* in_sizes, int n_in,
                              void* d_out, int out_size) {
    const float* hidden = (const float*)d_in[0];
    const float* ln1    = (const float*)d_in[1];
    const float* wq     = (const float*)d_in[2];
    const float* wk     = (const float*)d_in[3];
    const float* wv     = (const float*)d_in[4];
    const float* wo     = (const float*)d_in[5];
    const float* ln2    = (const float*)d_in[6];
    const float* rwt    = (const float*)d_in[7];
    const float* rb     = (const float*)d_in[8];
    const float* gw     = (const float*)d_in[9];
    const float* uw     = (const float*)d_in[10];
    const float* dw     = (const float*)d_in[11];
    float* out = (float*)d_out;

    float *pX, *pQ, *pK, *pV, *pO, *pH1, *pX2, *pS, *pRW, *pG, *pGU;
    cudaGetSymbolAddress((void**)&pX,  g_X);
    cudaGetSymbolAddress((void**)&pQ,  g_Q);
    cudaGetSymbolAddress((void**)&pK,  g_K);
    cudaGetSymbolAddress((void**)&pV,  g_V);
    cudaGetSymbolAddress((void**)&pO,  g_O);
    cudaGetSymbolAddress((void**)&pH1, g_H1);
    cudaGetSymbolAddress((void**)&pX2, g_X2);
    cudaGetSymbolAddress((void**)&pS,  g_S);
    cudaGetSymbolAddress((void**)&pRW, g_RW);
    cudaGetSymbolAddress((void**)&pG,  g_G);
    cudaGetSymbolAddress((void**)&pGU, g_GU);

    const dim3 blk(256);
    const long long ZERO = 0;

    // 1) x = rms(hidden, ln1)
    rms_k<<<Tq, 256>>>(hidden, ln1, pX);

    // 2) QKV projections (elu+1 fused for Q,K)
    dim3 g1(HIDq / 128, Tq / 128, 1);
    gemm_k<EPI_ELU1, false><<<g1, blk>>>(Tq, HIDq, HIDq,
        pX, HIDq, ZERO, ZERO, wq, HIDq, ZERO, ZERO, pQ, HIDq, ZERO, ZERO, nullptr, nullptr, 0);
    gemm_k<EPI_ELU1, false><<<g1, blk>>>(Tq, HIDq, HIDq,
        pX, HIDq, ZERO, ZERO, wk, HIDq, ZERO, ZERO, pK, HIDq, ZERO, ZERO, nullptr, nullptr, 0);
    gemm_k<EPI_NONE, false><<<g1, blk>>>(Tq, HIDq, HIDq,
        pX, HIDq, ZERO, ZERO, wv, HIDq, ZERO, ZERO, pV, HIDq, ZERO, ZERO, nullptr, nullptr, 0);

    // 3) scores = Q_head @ K_head^T  (batched over 16 (b,h) pairs)
    dim3 g2(Sq / 128, Sq / 128, Bq * NHq);
    gemm_k<EPI_NONE, true><<<g2, blk>>>(Sq, Sq, Dq,
        pQ, HIDq, (long long)Sq * HIDq, (long long)Dq,
        pK, HIDq, (long long)Sq * HIDq, (long long)Dq,
        pS, Sq,   (long long)NHq * Sq * Sq, (long long)Sq * Sq,
        nullptr, nullptr, 0);

    // 4) row softmax
    softmax_k<<<Bq * NHq * Sq, 256>>>(pS);

    // 5) O = attn @ V_head
    dim3 g3(Dq / 128, Sq / 128, Bq * NHq);
    gemm_k<EPI_NONE, false><<<g3, blk>>>(Sq, Dq, Sq,
        pS, Sq,   (long long)NHq * Sq * Sq, (long long)Sq * Sq,
        pV, HIDq, (long long)Sq * HIDq, (long long)Dq,
        pO, HIDq, (long long)Sq * HIDq, (long long)Dq,
        nullptr, nullptr, 0);

    // 6) h1 = hidden + O @ wo
    gemm_k<EPI_ADD, false><<<g1, blk>>>(Tq, HIDq, HIDq,
        pO, HIDq, ZERO, ZERO, wo, HIDq, ZERO, ZERO, pH1, HIDq, ZERO, ZERO, hidden, nullptr, 0);

    // 7) x2 = rms(h1, ln2)
    rms_k<<<Tq, 256>>>(pH1, ln2, pX2);

    // 8) router softmax weights
    router_k<<<Tq / 8, 256>>>(pX2, rwt, rb, pRW);

    // 9) balance loss -> tail of out (if present)
    balance_k<<<1, 1024>>>(pRW, out, (long long)Tq * HIDq, (long long)out_size);

    // 10) out[0 : T*HID) = h1
    cudaMemcpyAsync(out, pH1, (size_t)Tq * HIDq * sizeof(float),
                    cudaMemcpyDeviceToDevice);

    // 11) dense MoE: out += silu(x2@gate)*(x2@up) @ down * rw[:,e]
    dim3 g4(IMq / 128, Tq / 128, 1);
    dim3 g5(HIDq / 128, Tq / 128, 1);
    for (int e = 0; e < Eq; e++) {
        const float* ge = gw + (long long)e * HIDq * IMq;
        const float* ue = uw + (long long)e * HIDq * IMq;
        const float* de = dw + (long long)e * IMq * HIDq;
        gemm_k<EPI_SILU, false><<<g4, blk>>>(Tq, IMq, HIDq,
            pX2, HIDq, ZERO, ZERO, ge, IMq, ZERO, ZERO, pG, IMq, ZERO, ZERO, nullptr, nullptr, 0);
        gemm_k<EPI_MUL, false><<<g4, blk>>>(Tq, IMq, HIDq,
            pX2, HIDq, ZERO, ZERO, ue, IMq, ZERO, ZERO, pGU, IMq, ZERO, ZERO, pG, nullptr, 0);
        gemm_k<EPI_SCALEACC, false><<<g5, blk>>>(Tq, HIDq, IMq,
            pGU, IMq, ZERO, ZERO, de, HIDq, ZERO, ZERO, out, HIDq, ZERO, ZERO,
            nullptr, pRW + e, Eq);
    }
}

// round 4
// speedup vs baseline: 1.3401x; 1.3401x over previous
#include <cuda_runtime.h>
#include <math.h>
#include <stdint.h>

#define Bq 4
#define Sq 2048
#define HIDq 1024
#define NHq 4
#define Dq 256
#define IMq 2048
#define Eq 4
#define Tq (Bq*Sq)

// ---------------- scratch ----------------
__device__ float g_Xhi[Tq*HIDq], g_Xlo[Tq*HIDq];
__device__ float g_Qhi[Tq*HIDq], g_Qlo[Tq*HIDq];
__device__ float g_Khi[Tq*HIDq], g_Klo[Tq*HIDq];
__device__ float g_Vf[Tq*HIDq];
__device__ float g_Vthi[HIDq*Tq], g_Vtlo[HIDq*Tq];
__device__ float g_S[67108864];
__device__ float g_Phi[67108864], g_Plo[67108864];
__device__ float g_Ohi[Tq*HIDq], g_Olo[Tq*HIDq];
__device__ float g_H1[Tq*HIDq], g_Xp[Tq*HIDq];
__device__ float g_X2hi[Tq*HIDq], g_X2lo[Tq*HIDq];
__device__ float g_G[Tq*IMq];
__device__ float g_GUhi[Tq*IMq], g_GUlo[Tq*IMq];
__device__ float g_RW[Tq*Eq];
__device__ float g_WqThi[HIDq*HIDq], g_WqTlo[HIDq*HIDq];
__device__ float g_WkThi[HIDq*HIDq], g_WkTlo[HIDq*HIDq];
__device__ float g_WvThi[HIDq*HIDq], g_WvTlo[HIDq*HIDq];
__device__ float g_WoThi[HIDq*HIDq], g_WoTlo[HIDq*HIDq];
__device__ float g_GThi[Eq*IMq*HIDq], g_GTlo[Eq*IMq*HIDq];
__device__ float g_UThi[Eq*IMq*HIDq], g_UTlo[Eq*IMq*HIDq];
__device__ float g_DThi[Eq*HIDq*IMq], g_DTlo[Eq*HIDq*IMq];

// ---------------- helpers ----------------
__device__ __forceinline__ uint32_t smem_u32(const void* p) {
    uint32_t a;
    asm("{ .reg .u64 t; cvta.to.shared.u64 t, %1; cvt.u32.u64 %0, t; }" : "=r"(a) : "l"(p));
    return a;
}
__device__ __forceinline__ float tf32r(float x) {
    uint32_t u; asm("cvt.rna.tf32.f32 %0, %1;" : "=r"(u) : "f"(x));
    return __uint_as_float(u);
}
#define MMA8(c, a0,a1,a2,a3, b0,b1) \
    asm volatile("mma.sync.aligned.m16n8k8.row.col.f32.tf32.tf32.f32 " \
        "{%0,%1,%2,%3}, {%4,%5,%6,%7}, {%8,%9}, {%0,%1,%2,%3};" \
        : "+f"((c)[0]), "+f"((c)[1]), "+f"((c)[2]), "+f"((c)[3]) \
        : "r"(a0), "r"(a1), "r"(a2), "r"(a3), "r"(b0), "r"(b1))

#define CPA16(s, g) asm volatile("cp.async.cg.shared.global [%0], [%1], 16;" :: "r"(s), "l"(g))
#define CPA_COMMIT() asm volatile("cp.async.commit_group;")

// ---------------- tf32x3 mma.sync GEMM: 128x128 tile, ktile 16 ----------------
// A: [M,K] row-major hi/lo.  B: [N,K] row-major hi/lo (i.e. column-major KxN).
enum { EPI_NONE = 0, EPI_ELU1, EPI_SILU, EPI_MUL, EPI_ADD, EPI_SCALEACC };
#define SMEM_DYN 81920   // 2 stages * 4 tiles * 128*20 floats

template<int EPI, bool SPLIT>
__global__ __launch_bounds__(256, 2)
void mgemm(int K,
           const float* __restrict__ Ahi, const float* __restrict__ Alo,
           int lda, long long sAb, long long sAh,
           const float* __restrict__ Bhi, const float* __restrict__ Blo,
           int ldb, long long sBb, long long sBh,
           float* C, float* Chi, float* Clo,
           int ldc, long long sCb, long long sCh,
           const float* __restrict__ Dp,
           const float* __restrict__ scale, int sstride) {
    extern __shared__ float smf[];
    const int t = threadIdx.x;
    const int lane = t & 31, wid = t >> 5;
    const int wm = wid & 1, wn = wid >> 1;      // warp tile: 64x32
    const int zb = blockIdx.z >> 2, zh = blockIdx.z & 3;
    const int row0 = blockIdx.y * 128, col0 = blockIdx.x * 128;

    Ahi += (long long)zb * sAb + (long long)zh * sAh;
    Alo += (long long)zb * sAb + (long long)zh * sAh;
    Bhi += (long long)zb * sBb + (long long)zh * sBh;
    Blo += (long long)zb * sBb + (long long)zh * sBh;
    const long long coff = (long long)zb * sCb + (long long)zh * sCh;

    float c[4][4][4];
    #pragma unroll
    for (int i = 0; i < 4; i++)
        #pragma unroll
        for (int j = 0; j < 4; j++)
            #pragma unroll
            for (int k = 0; k < 4; k++) c[i][j][k] = 0.f;

    const int nkt = K >> 4;

    // smem layout per stage (floats): Ah[128*20] Al Bh Bl ; stage stride 10240
    auto stage = [&](int kt, int buf) {
        const int k0 = kt << 4;
        float* sb = smf + buf * 10240;
        #pragma unroll
        for (int i = 0; i < 8; i++) {
            int chunk = t + (i << 8);
            int tile = chunk >> 9;          // 512 chunks per tile
            int idx = chunk & 511;
            int row = idx >> 2;
            int q = (idx & 3) << 2;
            const float* g;
            if (tile == 0)      g = Ahi + (long long)(row0 + row) * lda + k0 + q;
            else if (tile == 1) g = Alo + (long long)(row0 + row) * lda + k0 + q;
            else if (tile == 2) g = Bhi + (long long)(col0 + row) * ldb + k0 + q;
            else                g = Blo + (long long)(col0 + row) * ldb + k0 + q;
            uint32_t s = smem_u32(sb + tile * 2560 + row * 20 + q);
            CPA16(s, g);
        }
        CPA_COMMIT();
    };

    stage(0, 0);

    for (int kt = 0; kt < nkt; kt++) {
        if (kt + 1 < nkt) {
            stage(kt + 1, (kt + 1) & 1);
            asm volatile("cp.async.wait_group 1;");
        } else {
            asm volatile("cp.async.wait_group 0;");
        }
        __syncthreads();
        const float* sb  = smf + (kt & 1) * 10240;
        const float* sAh = sb;
        const float* sAl = sb + 2560;
        const float* sBh = sb + 5120;
        const float* sBl = sb + 7680;

        #pragma unroll
        for (int k8 = 0; k8 < 2; k8++) {
            const int kq = (k8 << 3) + (lane & 3);
            uint32_t bh[4][2], bl[4][2];
            #pragma unroll
            for (int nt = 0; nt < 4; nt++) {
                const int off = (wn * 32 + nt * 8 + (lane >> 2)) * 20 + kq;
                bh[nt][0] = __float_as_uint(sBh[off]);
                bh[nt][1] = __float_as_uint(sBh[off + 4]);
                bl[nt][0] = __float_as_uint(sBl[off]);
                bl[nt][1] = __float_as_uint(sBl[off + 4]);
            }
            #pragma unroll
            for (int mt = 0; mt < 4; mt++) {
                const int off = (wm * 64 + mt * 16 + (lane >> 2)) * 20 + kq;
                uint32_t ah[4], al[4];
                ah[0] = __float_as_uint(sAh[off]);
                ah[1] = __float_as_uint(sAh[off + 160]);
                ah[2] = __float_as_uint(sAh[off + 4]);
                ah[3] = __float_as_uint(sAh[off + 164]);
                al[0] = __float_as_uint(sAl[off]);
                al[1] = __float_as_uint(sAl[off + 160]);
                al[2] = __float_as_uint(sAl[off + 4]);
                al[3] = __float_as_uint(sAl[off + 164]);
                #pragma unroll
                for (int nt = 0; nt < 4; nt++) {
                    MMA8(c[mt][nt], ah[0], ah[1], ah[2], ah[3], bh[nt][0], bh[nt][1]);
                    MMA8(c[mt][nt], ah[0], ah[1], ah[2], ah[3], bl[nt][0], bl[nt][1]);
                    MMA8(c[mt][nt], al[0], al[1], al[2], al[3], bh[nt][0], bh[nt][1]);
                }
            }
        }
        __syncthreads();
    }

    // ---------------- epilogue ----------------
    #pragma unroll
    for (int mt = 0; mt < 4; mt++) {
        #pragma unroll
        for (int half = 0; half < 2; half++) {
            const long long r = row0 + wm * 64 + mt * 16 + (lane >> 2) + half * 8;
            float sc = 0.f;
            if (EPI == EPI_SCALEACC) sc = __ldg(scale + r * sstride);
            #pragma unroll
            for (int nt = 0; nt < 4; nt++) {
                const long long gi = r * ldc + col0 + wn * 32 + nt * 8 + (lane & 3) * 2;
                float v0 = c[mt][nt][half * 2 + 0];
                float v1 = c[mt][nt][half * 2 + 1];
                if (EPI == EPI_ELU1) {
                    v0 = (v0 >= 0.f) ? v0 + 1.f : expf(v0);
                    v1 = (v1 >= 0.f) ? v1 + 1.f : expf(v1);
                } else if (EPI == EPI_SILU) {
                    v0 = v0 / (1.f + expf(-v0));
                    v1 = v1 / (1.f + expf(-v1));
                } else if (EPI == EPI_MUL) {
                    float2 d = *(const float2*)(Dp + gi);
                    v0 *= d.x; v1 *= d.y;
                } else if (EPI == EPI_ADD) {
                    float2 d = *(const float2*)(Dp + gi);
                    v0 += d.x; v1 += d.y;
                } else if (EPI == EPI_SCALEACC) {
                    float2 cc = *(const float2*)(C + coff + gi);
                    v0 = fmaf(v0, sc, cc.x); v1 = fmaf(v1, sc, cc.y);
                }
                if (SPLIT) {
                    float h0 = tf32r(v0), h1 = tf32r(v1);
                    *(float2*)(Chi + coff + gi) = make_float2(h0, h1);
                    *(float2*)(Clo + coff + gi) = make_float2(tf32r(v0 - h0), tf32r(v1 - h1));
                } else {
                    *(float2*)(C + coff + gi) = make_float2(v0, v1);
                }
            }
        }
    }
}

// ---------------- reductions ----------------
__device__ __forceinline__ float blk_sum(float v, float* sh) {
    __syncthreads();
    int t = threadIdx.x, lane = t & 31, w = t >> 5;
    #pragma unroll
    for (int o = 16; o; o >>= 1) v += __shfl_down_sync(0xffffffffu, v, o);
    if (lane == 0) sh[w] = v;
    __syncthreads();
    float r = (t < (int)(blockDim.x >> 5)) ? sh[t] : 0.f;
    if (w == 0) {
        #pragma unroll
        for (int o = 16; o; o >>= 1) r += __shfl_down_sync(0xffffffffu, r, o);
        if (t == 0) sh[0] = r;
    }
    __syncthreads();
    return sh[0];
}
__device__ __forceinline__ float blk_max(float v, float* sh) {
    __syncthreads();
    int t = threadIdx.x, lane = t & 31, w = t >> 5;
    #pragma unroll
    for (int o = 16; o; o >>= 1) v = fmaxf(v, __shfl_down_sync(0xffffffffu, v, o));
    if (lane == 0) sh[w] = v;
    __syncthreads();
    float r = (t < (int)(blockDim.x >> 5)) ? sh[t] : -1e30f;
    if (w == 0) {
        #pragma unroll
        for (int o = 16; o; o >>= 1) r = fmaxf(r, __shfl_down_sync(0xffffffffu, r, o));
        if (t == 0) sh[0] = r;
    }
    __syncthreads();
    return sh[0];
}

// ---------------- RMSNorm + tf32 split ----------------
__global__ void rms_k(const float* __restrict__ x, const float* __restrict__ w,
                      float* __restrict__ y, float* __restrict__ yhi, float* __restrict__ ylo) {
    __shared__ float sh[32];
    long long row = blockIdx.x;
    const float4 xv = *(const float4*)(x + row * HIDq + threadIdx.x * 4);
    float ss = xv.x*xv.x + xv.y*xv.y + xv.z*xv.z + xv.w*xv.w;
    ss = blk_sum(ss, sh);
    float inv = rsqrtf(ss * (1.0f / HIDq) + 1e-6f);
    const float4 wv = *(const float4*)(w + threadIdx.x * 4);
    float v[4] = { xv.x*inv*wv.x, xv.y*inv*wv.y, xv.z*inv*wv.z, xv.w*inv*wv.w };
    float4 p, h, l;
    #pragma unroll
    for (int i = 0; i < 4; i++) {
        ((float*)&p)[i] = v[i];
        float hh = tf32r(v[i]);
        ((float*)&h)[i] = hh;
        ((float*)&l)[i] = tf32r(v[i] - hh);
    }
    *(float4*)(y   + row * HIDq + threadIdx.x * 4) = p;
    *(float4*)(yhi + row * HIDq + threadIdx.x * 4) = h;
    *(float4*)(ylo + row * HIDq + threadIdx.x * 4) = l;
}

// ---------------- softmax + split ----------------
__global__ void softmax_k(const float* __restrict__ s,
                          float* __restrict__ phi, float* __restrict__ plo) {
    __shared__ float sh[32];
    long long base = (long long)blockIdx.x * Sq;
    int t = threadIdx.x;
    float v[8]; float mx = -1e30f;
    #pragma unroll
    for (int i = 0; i < 8; i++) { v[i] = s[base + t + 256*i]; mx = fmaxf(mx, v[i]); }
    mx = blk_max(mx, sh);
    float sum = 0.f;
    #pragma unroll
    for (int i = 0; i < 8; i++) { v[i] = expf(v[i] - mx); sum += v[i]; }
    sum = blk_sum(sum, sh);
    float inv = 1.0f / sum;
    #pragma unroll
    for (int i = 0; i < 8; i++) {
        float p = v[i] * inv;
        float h = tf32r(p);
        phi[base + t + 256*i] = h;
        plo[base + t + 256*i] = tf32r(p - h);
    }
}

// ---------------- transpose + split ----------------
__global__ void tsplit_k(const float* __restrict__ in, float* __restrict__ ohi,
                         float* __restrict__ olo, int ldin, int ldout,
                         long long sIb, long long sIh, long long sOb, long long sOh) {
    __shared__ float tile[32][33];
    int z = blockIdx.z, zb = z >> 2, zh = z & 3;
    in  += (long long)zb * sIb + (long long)zh * sIh;
    ohi += (long long)zb * sOb + (long long)zh * sOh;
    olo += (long long)zb * sOb + (long long)zh * sOh;
    int r0 = blockIdx.y * 32, c0 = blockIdx.x * 32;
    int tx = threadIdx.x, ty = threadIdx.y;
    #pragma unroll
    for (int k = 0; k < 4; k++)
        tile[ty + 8*k][tx] = in[(long long)(r0 + ty + 8*k) * ldin + c0 + tx];
    __syncthreads();
    #pragma unroll
    for (int k = 0; k < 4; k++) {
        float v = tile[tx][ty + 8*k];
        long long oi = (long long)(c0 + ty + 8*k) * ldout + r0 + tx;
        float h = tf32r(v);
        ohi[oi] = h;
        olo[oi] = tf32r(v - h);
    }
}

// ---------------- router ----------------
__global__ void router_k(const float* __restrict__ x2, const float* __restrict__ rwt,
                         const float* __restrict__ rb, float* __restrict__ rw) {
    int warp = threadIdx.x >> 5, lane = threadIdx.x & 31;
    long long token = (long long)blockIdx.x * (blockDim.x >> 5) + warp;
    const float* xr = x2 + token * HIDq;
    float a0=0.f, a1=0.f, a2=0.f, a3=0.f;
    for (int k = lane; k < HIDq; k += 32) {
        float xv = xr[k];
        float4 w4 = *(const float4*)(rwt + (long long)k * Eq);
        a0 = fmaf(xv, w4.x, a0); a1 = fmaf(xv, w4.y, a1);
        a2 = fmaf(xv, w4.z, a2); a3 = fmaf(xv, w4.w, a3);
    }
    #pragma unroll
    for (int o = 16; o; o >>= 1) {
        a0 += __shfl_down_sync(0xffffffffu, a0, o);
        a1 += __shfl_down_sync(0xffffffffu, a1, o);
        a2 += __shfl_down_sync(0xffffffffu, a2, o);
        a3 += __shfl_down_sync(0xffffffffu, a3, o);
    }
    if (lane == 0) {
        float l0=a0+rb[0], l1=a1+rb[1], l2=a2+rb[2], l3=a3+rb[3];
        float m = fmaxf(fmaxf(l0,l1), fmaxf(l2,l3));
        float e0=expf(l0-m), e1=expf(l1-m), e2=expf(l2-m), e3=expf(l3-m);
        float inv = 1.0f / (e0+e1+e2+e3);
        float4 o4; o4.x=e0*inv; o4.y=e1*inv; o4.z=e2*inv; o4.w=e3*inv;
        *(float4*)(rw + token * Eq) = o4;
    }
}

// ---------------- balance loss ----------------
__global__ void balance_k(const float* __restrict__ rw, float* __restrict__ out,
                          long long tail_begin, long long out_size) {
    __shared__ float red[1024];
    int t = threadIdx.x;
    float s = 0.f;
    for (int idx = t; idx < Sq * Eq; idx += 1024) {
        int srow = idx / Eq, e = idx % Eq;
        float m = 0.f;
        #pragma unroll
        for (int b = 0; b < Bq; b++) m += rw[((long long)b * Sq + srow) * Eq + e];
        m *= (1.0f / Bq);
        float d = m - 1.0f / Eq;
        s += d * d;
    }
    red[t] = s;
    __syncthreads();
    for (int o = 512; o; o >>= 1) { if (t < o) red[t] += red[t + o]; __syncthreads(); }
    if (t == 0) {
        float loss = red[0] / ((float)Sq * Eq) * 0.01f;
        for (long long i = tail_begin; i < out_size; i++) out[i] = loss;
    }
}

// ---------------- host ----------------
#define SYM(p, s) float* p; cudaGetSymbolAddress((void**)&p, s)

extern "C" void kernel_launch(void* const* d_in, const int* in_sizes, int n_in,
                              void* d_out, int out_size) {
    const float* hidden = (const float*)d_in[0];
    const float* ln1 = (const float*)d_in[1];
    const float* wq = (const float*)d_in[2];
    const float* wk = (const float*)d_in[3];
    const float* wv = (const float*)d_in[4];
    const float* wo = (const float*)d_in[5];
    const float* ln2 = (const float*)d_in[6];
    const float* rwt = (const float*)d_in[7];
    const float* rb = (const float*)d_in[8];
    const float* gw = (const float*)d_in[9];
    const float* uw = (const float*)d_in[10];
    const float* dwn = (const float*)d_in[11];
    float* out = (float*)d_out;

    SYM(pXhi, g_Xhi); SYM(pXlo, g_Xlo); SYM(pQhi, g_Qhi); SYM(pQlo, g_Qlo);
    SYM(pKhi, g_Khi); SYM(pKlo, g_Klo); SYM(pVf, g_Vf);
    SYM(pVthi, g_Vthi); SYM(pVtlo, g_Vtlo);
    SYM(pS, g_S); SYM(pPhi, g_Phi); SYM(pPlo, g_Plo);
    SYM(pOhi, g_Ohi); SYM(pOlo, g_Olo); SYM(pH1, g_H1); SYM(pXp, g_Xp);
    SYM(pX2hi, g_X2hi); SYM(pX2lo, g_X2lo);
    SYM(pG, g_G); SYM(pGUhi, g_GUhi); SYM(pGUlo, g_GUlo); SYM(pRW, g_RW);
    SYM(pWqThi, g_WqThi); SYM(pWqTlo, g_WqTlo);
    SYM(pWkThi, g_WkThi); SYM(pWkTlo, g_WkTlo);
    SYM(pWvThi, g_WvThi); SYM(pWvTlo, g_WvTlo);
    SYM(pWoThi, g_WoThi); SYM(pWoTlo, g_WoTlo);
    SYM(pGThi, g_GThi); SYM(pGTlo, g_GTlo);
    SYM(pUThi, g_UThi); SYM(pUTlo, g_UTlo);
    SYM(pDThi, g_DThi); SYM(pDTlo, g_DTlo);

    cudaFuncSetAttribute(mgemm<EPI_ELU1,true>,     cudaFuncAttributeMaxDynamicSharedMemorySize, SMEM_DYN);
    cudaFuncSetAttribute(mgemm<EPI_NONE,false>,    cudaFuncAttributeMaxDynamicSharedMemorySize, SMEM_DYN);
    cudaFuncSetAttribute(mgemm<EPI_NONE,true>,     cudaFuncAttributeMaxDynamicSharedMemorySize, SMEM_DYN);
    cudaFuncSetAttribute(mgemm<EPI_ADD,false>,     cudaFuncAttributeMaxDynamicSharedMemorySize, SMEM_DYN);
    cudaFuncSetAttribute(mgemm<EPI_SILU,false>,    cudaFuncAttributeMaxDynamicSharedMemorySize, SMEM_DYN);
    cudaFuncSetAttribute(mgemm<EPI_MUL,true>,      cudaFuncAttributeMaxDynamicSharedMemorySize, SMEM_DYN);
    cudaFuncSetAttribute(mgemm<EPI_SCALEACC,false>,cudaFuncAttributeMaxDynamicSharedMemorySize, SMEM_DYN);

    const long long Z = 0;
    const dim3 tb(32, 8);

    // 1) rms1 + split
    rms_k<<<Tq, 256>>>(hidden, ln1, pXp, pXhi, pXlo);

    // 2) weight transposes + split (to [N,K] layout)
    tsplit_k<<<dim3(32,32,1), tb>>>(wq, pWqThi, pWqTlo, HIDq, HIDq, Z,Z,Z,Z);
    tsplit_k<<<dim3(32,32,1), tb>>>(wk, pWkThi, pWkTlo, HIDq, HIDq, Z,Z,Z,Z);
    tsplit_k<<<dim3(32,32,1), tb>>>(wv, pWvThi, pWvTlo, HIDq, HIDq, Z,Z,Z,Z);
    tsplit_k<<<dim3(32,32,1), tb>>>(wo, pWoThi, pWoTlo, HIDq, HIDq, Z,Z,Z,Z);
    tsplit_k<<<dim3(64,32,4), tb>>>(gw, pGThi, pGTlo, IMq, HIDq, Z,(long long)HIDq*IMq, Z,(long long)IMq*HIDq);
    tsplit_k<<<dim3(64,32,4), tb>>>(uw, pUThi, pUTlo, IMq, HIDq, Z,(long long)HIDq*IMq, Z,(long long)IMq*HIDq);
    tsplit_k<<<dim3(32,64,4), tb>>>(dwn, pDThi, pDTlo, HIDq, IMq, Z,(long long)IMq*HIDq, Z,(long long)HIDq*IMq);

    // 3) QKV projections
    dim3 gQKV(HIDq/128, Tq/128, 1);
    mgemm<EPI_ELU1,true><<<gQKV, 256, SMEM_DYN>>>(HIDq,
        pXhi, pXlo, HIDq, Z,Z, pWqThi, pWqTlo, HIDq, Z,Z,
        nullptr, pQhi, pQlo, HIDq, Z,Z, nullptr, nullptr, 0);
    mgemm<EPI_ELU1,true><<<gQKV, 256, SMEM_DYN>>>(HIDq,
        pXhi, pXlo, HIDq, Z,Z, pWkThi, pWkTlo, HIDq, Z,Z,
        nullptr, pKhi, pKlo, HIDq, Z,Z, nullptr, nullptr, 0);
    mgemm<EPI_NONE,false><<<gQKV, 256, SMEM_DYN>>>(HIDq,
        pXhi, pXlo, HIDq, Z,Z, pWvThi, pWvTlo, HIDq, Z,Z,
        pVf, nullptr, nullptr, HIDq, Z,Z, nullptr, nullptr, 0);

    // 4) V transpose per (b,h): [2048 x 256] -> [256 x 2048] hi/lo
    tsplit_k<<<dim3(8,64,16), tb>>>(pVf, pVthi, pVtlo, HIDq, Sq,
        (long long)Sq*HIDq, (long long)Dq,
        (long long)NHq*Dq*Sq, (long long)Dq*Sq);

    // 5) scores = Q @ K^T per head
    mgemm<EPI_NONE,false><<<dim3(16,16,16), 256, SMEM_DYN>>>(Dq,
        pQhi, pQlo, HIDq, (long long)Sq*HIDq, (long long)Dq,
        pKhi, pKlo, HIDq, (long long)Sq*HIDq, (long long)Dq,
        pS, nullptr, nullptr, Sq, (long long)NHq*Sq*Sq, (long long)Sq*Sq,
        nullptr, nullptr, 0);

    // 6) softmax + split
    softmax_k<<<Bq*NHq*Sq, 256>>>(pS, pPhi, pPlo);

    // 7) O = P @ V per head (split output)
    mgemm<EPI_NONE,true><<<dim3(2,16,16), 256, SMEM_DYN>>>(Sq,
        pPhi, pPlo, Sq, (long long)NHq*Sq*Sq, (long long)Sq*Sq,
        pVthi, pVtlo, Sq, (long long)NHq*Dq*Sq, (long long)Dq*Sq,
        nullptr, pOhi, pOlo, HIDq, (long long)Sq*HIDq, (long long)Dq,
        nullptr, nullptr, 0);

    // 8) h1 = hidden + O @ wo
    mgemm<EPI_ADD,false><<<gQKV, 256, SMEM_DYN>>>(HIDq,
        pOhi, pOlo, HIDq, Z,Z, pWoThi, pWoTlo, HIDq, Z,Z,
        pH1, nullptr, nullptr, HIDq, Z,Z, hidden, nullptr, 0);

    // 9) rms2 + split, router, balance
    rms_k<<<Tq, 256>>>(pH1, ln2, pXp, pX2hi, pX2lo);
    router_k<<<Tq/8, 256>>>(pXp, rwt, rb, pRW);
    balance_k<<<1, 1024>>>(pRW, out, (long long)Tq*HIDq, (long long)out_size);

    // 10) out = h1, then MoE accumulation
    cudaMemcpyAsync(out, pH1, (size_t)Tq*HIDq*sizeof(float), cudaMemcpyDeviceToDevice);

    dim3 gGU(IMq/128, Tq/128, 1);
    dim3 gDN(HIDq/128, Tq/128, 1);
    for (int e = 0; e < Eq; e++) {
        float* gt = pGThi + (long long)e*IMq*HIDq;  float* gtl = pGTlo + (long long)e*IMq*HIDq;
        float* ut = pUThi + (long long)e*IMq*HIDq;  float* utl = pUTlo + (long long)e*IMq*HIDq;
        float* dt = pDThi + (long long)e*HIDq*IMq;  float* dtl = pDTlo + (long long)e*HIDq*IMq;
        mgemm<EPI_SILU,false><<<gGU, 256, SMEM_DYN>>>(HIDq,
            pX2hi, pX2lo, HIDq, Z,Z, gt, gtl, HIDq, Z,Z,
            pG, nullptr, nullptr, IMq, Z,Z, nullptr, nullptr, 0);
        mgemm<EPI_MUL,true><<<gGU, 256, SMEM_DYN>>>(HIDq,
            pX2hi, pX2lo, HIDq, Z,Z, ut, utl, HIDq, Z,Z,
            nullptr, pGUhi, pGUlo, IMq, Z,Z, pG, nullptr, 0);
        mgemm<EPI_SCALEACC,false><<<gDN, 256, SMEM_DYN>>>(IMq,
            pGUhi, pGUlo, IMq, Z,Z, dt, dtl, IMq, Z,Z,
            out, nullptr, nullptr, HIDq, Z,Z, nullptr, pRW + e, Eq);
    }
}

// round 5
// speedup vs baseline: 2.6744x; 1.9957x over previous
#include <cuda_runtime.h>
#include <cuda_bf16.h>
#include <math.h>
#include <stdint.h>

#define Bq 4
#define Sq 2048
#define HIDq 1024
#define NHq 4
#define Dq 256
#define IMq 2048
#define Eq 4
#define Tq (Bq*Sq)

typedef __nv_bfloat16 bf16;

// ---------------- scratch ----------------
__device__ bf16 g_Xhi[Tq*HIDq], g_Xlo[Tq*HIDq];
__device__ bf16 g_Qhi[Tq*HIDq], g_Qlo[Tq*HIDq];
__device__ bf16 g_Khi[Tq*HIDq], g_Klo[Tq*HIDq];
__device__ float g_Vf[Tq*HIDq];
__device__ bf16 g_Vthi[HIDq*Tq], g_Vtlo[HIDq*Tq];
__device__ float g_S[67108864];
__device__ bf16 g_Phi[67108864], g_Plo[67108864];
__device__ bf16 g_Ohi[Tq*HIDq], g_Olo[Tq*HIDq];
__device__ float g_H1[Tq*HIDq], g_Xp[Tq*HIDq];
__device__ bf16 g_X2hi[Tq*HIDq], g_X2lo[Tq*HIDq];
__device__ float g_G[Tq*IMq];
__device__ bf16 g_GUhi[Tq*IMq], g_GUlo[Tq*IMq];
__device__ float g_RW[Tq*Eq];
__device__ bf16 g_WqThi[HIDq*HIDq], g_WqTlo[HIDq*HIDq];
__device__ bf16 g_WkThi[HIDq*HIDq], g_WkTlo[HIDq*HIDq];
__device__ bf16 g_WvThi[HIDq*HIDq], g_WvTlo[HIDq*HIDq];
__device__ bf16 g_WoThi[HIDq*HIDq], g_WoTlo[HIDq*HIDq];
__device__ bf16 g_GThi[Eq*IMq*HIDq], g_GTlo[Eq*IMq*HIDq];
__device__ bf16 g_UThi[Eq*IMq*HIDq], g_UTlo[Eq*IMq*HIDq];
__device__ bf16 g_DThi[Eq*HIDq*IMq], g_DTlo[Eq*HIDq*IMq];

// ---------------- helpers ----------------
__device__ __forceinline__ uint32_t smem_u32(const void* p) {
    uint32_t a;
    asm("{ .reg .u64 t; cvta.to.shared.u64 t, %1; cvt.u32.u64 %0, t; }" : "=r"(a) : "l"(p));
    return a;
}
__device__ __forceinline__ void bsplit(float v, bf16& h, bf16& l) {
    h = __float2bfloat16(v);
    l = __float2bfloat16(v - __bfloat162float(h));
}
#define MMAB(c, a0,a1,a2,a3, b0,b1) \
    asm volatile("mma.sync.aligned.m16n8k16.row.col.f32.bf16.bf16.f32 " \
        "{%0,%1,%2,%3}, {%4,%5,%6,%7}, {%8,%9}, {%0,%1,%2,%3};" \
        : "+f"((c)[0]), "+f"((c)[1]), "+f"((c)[2]), "+f"((c)[3]) \
        : "r"(a0), "r"(a1), "r"(a2), "r"(a3), "r"(b0), "r"(b1))
#define LDSM4(r0,r1,r2,r3, addr) \
    asm volatile("ldmatrix.sync.aligned.m8n8.x4.shared.b16 {%0,%1,%2,%3}, [%4];" \
        : "=r"(r0), "=r"(r1), "=r"(r2), "=r"(r3) : "r"(addr))
#define LDSM2(r0,r1, addr) \
    asm volatile("ldmatrix.sync.aligned.m8n8.x2.shared.b16 {%0,%1}, [%2];" \
        : "=r"(r0), "=r"(r1) : "r"(addr))
#define CPA16(s, g) asm volatile("cp.async.cg.shared.global [%0], [%1], 16;" :: "r"(s), "l"(g))
#define CPA_COMMIT() asm volatile("cp.async.commit_group;")

// ---------------- bf16x3 mma.sync GEMM: 128x128 tile, ktile 32 ----------------
// A: [M,K] row-major bf16 hi/lo.  B: [N,K] row-major bf16 hi/lo.
enum { EPI_NONE = 0, EPI_ELU1, EPI_SILU, EPI_MUL, EPI_ADD, EPI_SCALEACC };
// per stage: 4 tiles of 128 rows * 80 bytes = 40960; 2 stages
#define TILE_B 10240
#define STAGE_B 40960
#define SMEM_DYN (2*STAGE_B)

template<int EPI, bool SPLIT>
__global__ __launch_bounds__(256, 2)
void mgemm(int K,
           const bf16* __restrict__ Ahi, const bf16* __restrict__ Alo,
           int lda, long long sAb, long long sAh,
           const bf16* __restrict__ Bhi, const bf16* __restrict__ Blo,
           int ldb, long long sBb, long long sBh,
           float* C, bf16* Chi, bf16* Clo,
           int ldc, long long sCb, long long sCh,
           const float* __restrict__ Dp,
           const float* __restrict__ scale, int sstride) {
    extern __shared__ char smc[];
    const int t = threadIdx.x;
    const int lane = t & 31, wid = t >> 5;
    const int wm = wid & 1, wn = wid >> 1;      // warp tile: 64(M) x 32(N)
    const int zb = blockIdx.z >> 2, zh = blockIdx.z & 3;
    const int row0 = blockIdx.y * 128, col0 = blockIdx.x * 128;

    Ahi += (long long)zb * sAb + (long long)zh * sAh;
    Alo += (long long)zb * sAb + (long long)zh * sAh;
    Bhi += (long long)zb * sBb + (long long)zh * sBh;
    Blo += (long long)zb * sBb + (long long)zh * sBh;
    const long long coff = (long long)zb * sCb + (long long)zh * sCh;

    float c[4][4][4];
    #pragma unroll
    for (int i = 0; i < 4; i++)
        #pragma unroll
        for (int j = 0; j < 4; j++)
            #pragma unroll
            for (int k = 0; k < 4; k++) c[i][j][k] = 0.f;

    const int nkt = K >> 5;
    const uint32_t smu = smem_u32(smc);

    // stage loader: 2048 chunks of 16B; 8 per thread
    auto stage = [&](int kt, int buf) {
        const int k0 = kt << 5;
        const uint32_t sb = smu + buf * STAGE_B;
        #pragma unroll
        for (int i = 0; i < 8; i++) {
            int chunk = t + (i << 8);
            int tile = chunk >> 9;
            int idx = chunk & 511;
            int row = idx >> 2;
            int q = idx & 3;           // 16B = 8 bf16
            const bf16* g;
            if (tile == 0)      g = Ahi + (long long)(row0 + row) * lda + k0 + q * 8;
            else if (tile == 1) g = Alo + (long long)(row0 + row) * lda + k0 + q * 8;
            else if (tile == 2) g = Bhi + (long long)(col0 + row) * ldb + k0 + q * 8;
            else                g = Blo + (long long)(col0 + row) * ldb + k0 + q * 8;
            CPA16(sb + tile * TILE_B + row * 80 + q * 16, g);
        }
        CPA_COMMIT();
    };

    stage(0, 0);

    for (int kt = 0; kt < nkt; kt++) {
        if (kt + 1 < nkt) {
            stage(kt + 1, (kt + 1) & 1);
            asm volatile("cp.async.wait_group 1;");
        } else {
            asm volatile("cp.async.wait_group 0;");
        }
        __syncthreads();
        const uint32_t sb  = smu + (kt & 1) * STAGE_B;
        const uint32_t sAh = sb;
        const uint32_t sAl = sb + TILE_B;
        const uint32_t sBh = sb + 2 * TILE_B;
        const uint32_t sBl = sb + 3 * TILE_B;

        #pragma unroll
        for (int k16 = 0; k16 < 2; k16++) {
            const int kc = k16 << 4;
            // B fragments
            uint32_t bh[4][2], bl[4][2];
            const uint32_t boff = (uint32_t)(wn * 32 + (lane & 7)) * 80
                                + (uint32_t)(kc + ((lane & 8) ? 8 : 0)) * 2;
            #pragma unroll
            for (int nt = 0; nt < 4; nt++) {
                LDSM2(bh[nt][0], bh[nt][1], sBh + boff + nt * 8 * 80);
                LDSM2(bl[nt][0], bl[nt][1], sBl + boff + nt * 8 * 80);
            }
            // A fragments + MMA
            const uint32_t aoff = (uint32_t)(wm * 64 + (lane & 15)) * 80
                                + (uint32_t)(kc + ((lane >> 4) << 3)) * 2;
            #pragma unroll
            for (int mt = 0; mt < 4; mt++) {
                uint32_t ah0, ah1, ah2, ah3, al0, al1, al2, al3;
                LDSM4(ah0, ah1, ah2, ah3, sAh + aoff + mt * 16 * 80);
                LDSM4(al0, al1, al2, al3, sAl + aoff + mt * 16 * 80);
                #pragma unroll
                for (int nt = 0; nt < 4; nt++) {
                    MMAB(c[mt][nt], ah0, ah1, ah2, ah3, bh[nt][0], bh[nt][1]);
                    MMAB(c[mt][nt], ah0, ah1, ah2, ah3, bl[nt][0], bl[nt][1]);
                    MMAB(c[mt][nt], al0, al1, al2, al3, bh[nt][0], bh[nt][1]);
                }
            }
        }
        __syncthreads();
    }

    // ---------------- epilogue ----------------
    #pragma unroll
    for (int mt = 0; mt < 4; mt++) {
        #pragma unroll
        for (int half = 0; half < 2; half++) {
            const long long r = row0 + wm * 64 + mt * 16 + (lane >> 2) + half * 8;
            float sc = 0.f;
            if (EPI == EPI_SCALEACC) sc = __ldg(scale + r * sstride);
            #pragma unroll
            for (int nt = 0; nt < 4; nt++) {
                const long long gi = r * ldc + col0 + wn * 32 + nt * 8 + (lane & 3) * 2;
                float v0 = c[mt][nt][half * 2 + 0];
                float v1 = c[mt][nt][half * 2 + 1];
                if (EPI == EPI_ELU1) {
                    v0 = (v0 >= 0.f) ? v0 + 1.f : expf(v0);
                    v1 = (v1 >= 0.f) ? v1 + 1.f : expf(v1);
                } else if (EPI == EPI_SILU) {
                    v0 = v0 / (1.f + expf(-v0));
                    v1 = v1 / (1.f + expf(-v1));
                } else if (EPI == EPI_MUL) {
                    float2 d = *(const float2*)(Dp + gi);
                    v0 *= d.x; v1 *= d.y;
                } else if (EPI == EPI_ADD) {
                    float2 d = *(const float2*)(Dp + gi);
                    v0 += d.x; v1 += d.y;
                } else if (EPI == EPI_SCALEACC) {
                    float2 cc = *(const float2*)(C + coff + gi);
                    v0 = fmaf(v0, sc, cc.x); v1 = fmaf(v1, sc, cc.y);
                }
                if (SPLIT) {
                    bf16 h0, l0, h1, l1;
                    bsplit(v0, h0, l0); bsplit(v1, h1, l1);
                    __nv_bfloat162 hp; hp.x = h0; hp.y = h1;
                    __nv_bfloat162 lp; lp.x = l0; lp.y = l1;
                    *(__nv_bfloat162*)(Chi + coff + gi) = hp;
                    *(__nv_bfloat162*)(Clo + coff + gi) = lp;
                } else {
                    *(float2*)(C + coff + gi) = make_float2(v0, v1);
                }
            }
        }
    }
}

// ---------------- reductions ----------------
__device__ __forceinline__ float blk_sum(float v, float* sh) {
    __syncthreads();
    int t = threadIdx.x, lane = t & 31, w = t >> 5;
    #pragma unroll
    for (int o = 16; o; o >>= 1) v += __shfl_down_sync(0xffffffffu, v, o);
    if (lane == 0) sh[w] = v;
    __syncthreads();
    float r = (t < (int)(blockDim.x >> 5)) ? sh[t] : 0.f;
    if (w == 0) {
        #pragma unroll
        for (int o = 16; o; o >>= 1) r += __shfl_down_sync(0xffffffffu, r, o);
        if (t == 0) sh[0] = r;
    }
    __syncthreads();
    return sh[0];
}
__device__ __forceinline__ float blk_max(float v, float* sh) {
    __syncthreads();
    int t = threadIdx.x, lane = t & 31, w = t >> 5;
    #pragma unroll
    for (int o = 16; o; o >>= 1) v = fmaxf(v, __shfl_down_sync(0xffffffffu, v, o));
    if (lane == 0) sh[w] = v;
    __syncthreads();
    float r = (t < (int)(blockDim.x >> 5)) ? sh[t] : -1e30f;
    if (w == 0) {
        #pragma unroll
        for (int o = 16; o; o >>= 1) r = fmaxf(r, __shfl_down_sync(0xffffffffu, r, o));
        if (t == 0) sh[0] = r;
    }
    __syncthreads();
    return sh[0];
}

// ---------------- RMSNorm + bf16 split ----------------
__global__ void rms_k(const float* __restrict__ x, const float* __restrict__ w,
                      float* __restrict__ y, bf16* __restrict__ yhi, bf16* __restrict__ ylo) {
    __shared__ float sh[32];
    long long row = blockIdx.x;
    const float4 xv = *(const float4*)(x + row * HIDq + threadIdx.x * 4);
    float ss = xv.x*xv.x + xv.y*xv.y + xv.z*xv.z + xv.w*xv.w;
    ss = blk_sum(ss, sh);
    float inv = rsqrtf(ss * (1.0f / HIDq) + 1e-6f);
    const float4 wv = *(const float4*)(w + threadIdx.x * 4);
    float v[4] = { xv.x*inv*wv.x, xv.y*inv*wv.y, xv.z*inv*wv.z, xv.w*inv*wv.w };
    float4 p;
    bf16 hb[4], lb[4];
    #pragma unroll
    for (int i = 0; i < 4; i++) {
        ((float*)&p)[i] = v[i];
        bsplit(v[i], hb[i], lb[i]);
    }
    *(float4*)(y + row * HIDq + threadIdx.x * 4) = p;
    *(uint2*)(yhi + row * HIDq + threadIdx.x * 4) = *(uint2*)hb;
    *(uint2*)(ylo + row * HIDq + threadIdx.x * 4) = *(uint2*)lb;
}

// ---------------- softmax + bf16 split ----------------
__global__ void softmax_k(const float* __restrict__ s,
                          bf16* __restrict__ phi, bf16* __restrict__ plo) {
    __shared__ float sh[32];
    long long base = (long long)blockIdx.x * Sq;
    int t = threadIdx.x;
    float v[8]; float mx = -1e30f;
    #pragma unroll
    for (int i = 0; i < 8; i++) { v[i] = s[base + t + 256*i]; mx = fmaxf(mx, v[i]); }
    mx = blk_max(mx, sh);
    float sum = 0.f;
    #pragma unroll
    for (int i = 0; i < 8; i++) { v[i] = expf(v[i] - mx); sum += v[i]; }
    sum = blk_sum(sum, sh);
    float inv = 1.0f / sum;
    #pragma unroll
    for (int i = 0; i < 8; i++) {
        bf16 h, l;
        bsplit(v[i] * inv, h, l);
        phi[base + t + 256*i] = h;
        plo[base + t + 256*i] = l;
    }
}

// ---------------- transpose + bf16 split ----------------
__global__ void tsplit_k(const float* __restrict__ in, bf16* __restrict__ ohi,
                         bf16* __restrict__ olo, int ldin, int ldout,
                         long long sIb, long long sIh, long long sOb, long long sOh) {
    __shared__ float tile[32][33];
    int z = blockIdx.z, zb = z >> 2, zh = z & 3;
    in  += (long long)zb * sIb + (long long)zh * sIh;
    ohi += (long long)zb * sOb + (long long)zh * sOh;
    olo += (long long)zb * sOb + (long long)zh * sOh;
    int r0 = blockIdx.y * 32, c0 = blockIdx.x * 32;
    int tx = threadIdx.x, ty = threadIdx.y;
    #pragma unroll
    for (int k = 0; k < 4; k++)
        tile[ty + 8*k][tx] = in[(long long)(r0 + ty + 8*k) * ldin + c0 + tx];
    __syncthreads();
    #pragma unroll
    for (int k = 0; k < 4; k++) {
        float v = tile[tx][ty + 8*k];
        long long oi = (long long)(c0 + ty + 8*k) * ldout + r0 + tx;
        bf16 h, l;
        bsplit(v, h, l);
        ohi[oi] = h;
        olo[oi] = l;
    }
}

// ---------------- router ----------------
__global__ void router_k(const float* __restrict__ x2, const float* __restrict__ rwt,
                         const float* __restrict__ rb, float* __restrict__ rw) {
    int warp = threadIdx.x >> 5, lane = threadIdx.x & 31;
    long long token = (long long)blockIdx.x * (blockDim.x >> 5) + warp;
    const float* xr = x2 + token * HIDq;
    float a0=0.f, a1=0.f, a2=0.f, a3=0.f;
    for (int k = lane; k < HIDq; k += 32) {
        float xv = xr[k];
        float4 w4 = *(const float4*)(rwt + (long long)k * Eq);
        a0 = fmaf(xv, w4.x, a0); a1 = fmaf(xv, w4.y, a1);
        a2 = fmaf(xv, w4.z, a2); a3 = fmaf(xv, w4.w, a3);
    }
    #pragma unroll
    for (int o = 16; o; o >>= 1) {
        a0 += __shfl_down_sync(0xffffffffu, a0, o);
        a1 += __shfl_down_sync(0xffffffffu, a1, o);
        a2 += __shfl_down_sync(0xffffffffu, a2, o);
        a3 += __shfl_down_sync(0xffffffffu, a3, o);
    }
    if (lane == 0) {
        float l0=a0+rb[0], l1=a1+rb[1], l2=a2+rb[2], l3=a3+rb[3];
        float m = fmaxf(fmaxf(l0,l1), fmaxf(l2,l3));
        float e0=expf(l0-m), e1=expf(l1-m), e2=expf(l2-m), e3=expf(l3-m);
        float inv = 1.0f / (e0+e1+e2+e3);
        float4 o4; o4.x=e0*inv; o4.y=e1*inv; o4.z=e2*inv; o4.w=e3*inv;
        *(float4*)(rw + token * Eq) = o4;
    }
}

// ---------------- balance loss ----------------
__global__ void balance_k(const float* __restrict__ rw, float* __restrict__ out,
                          long long tail_begin, long long out_size) {
    __shared__ float red[1024];
    int t = threadIdx.x;
    float s = 0.f;
    for (int idx = t; idx < Sq * Eq; idx += 1024) {
        int srow = idx / Eq, e = idx % Eq;
        float m = 0.f;
        #pragma unroll
        for (int b = 0; b < Bq; b++) m += rw[((long long)b * Sq + srow) * Eq + e];
        m *= (1.0f / Bq);
        float d = m - 1.0f / Eq;
        s += d * d;
    }
    red[t] = s;
    __syncthreads();
    for (int o = 512; o; o >>= 1) { if (t < o) red[t] += red[t + o]; __syncthreads(); }
    if (t == 0) {
        float loss = red[0] / ((float)Sq * Eq) * 0.01f;
        for (long long i = tail_begin; i < out_size; i++) out[i] = loss;
    }
}

// ---------------- host ----------------
#define SYMF(p, s) float* p; cudaGetSymbolAddress((void**)&p, s)
#define SYMB(p, s) bf16* p; cudaGetSymbolAddress((void**)&p, s)

extern "C" void kernel_launch(void* const* d_in, const int* in_sizes, int n_in,
                              void* d_out, int out_size) {
    const float* hidden = (const float*)d_in[0];
    const float* ln1 = (const float*)d_in[1];
    const float* wq = (const float*)d_in[2];
    const float* wk = (const float*)d_in[3];
    const float* wv = (const float*)d_in[4];
    const float* wo = (const float*)d_in[5];
    const float* ln2 = (const float*)d_in[6];
    const float* rwt = (const float*)d_in[7];
    const float* rb = (const float*)d_in[8];
    const float* gw = (const float*)d_in[9];
    const float* uw = (const float*)d_in[10];
    const float* dwn = (const float*)d_in[11];
    float* out = (float*)d_out;

    SYMB(pXhi, g_Xhi); SYMB(pXlo, g_Xlo); SYMB(pQhi, g_Qhi); SYMB(pQlo, g_Qlo);
    SYMB(pKhi, g_Khi); SYMB(pKlo, g_Klo); SYMF(pVf, g_Vf);
    SYMB(pVthi, g_Vthi); SYMB(pVtlo, g_Vtlo);
    SYMF(pS, g_S); SYMB(pPhi, g_Phi); SYMB(pPlo, g_Plo);
    SYMB(pOhi, g_Ohi); SYMB(pOlo, g_Olo); SYMF(pH1, g_H1); SYMF(pXp, g_Xp);
    SYMB(pX2hi, g_X2hi); SYMB(pX2lo, g_X2lo);
    SYMF(pG, g_G); SYMB(pGUhi, g_GUhi); SYMB(pGUlo, g_GUlo); SYMF(pRW, g_RW);
    SYMB(pWqThi, g_WqThi); SYMB(pWqTlo, g_WqTlo);
    SYMB(pWkThi, g_WkThi); SYMB(pWkTlo, g_WkTlo);
    SYMB(pWvThi, g_WvThi); SYMB(pWvTlo, g_WvTlo);
    SYMB(pWoThi, g_WoThi); SYMB(pWoTlo, g_WoTlo);
    SYMB(pGThi, g_GThi); SYMB(pGTlo, g_GTlo);
    SYMB(pUThi, g_UThi); SYMB(pUTlo, g_UTlo);
    SYMB(pDThi, g_DThi); SYMB(pDTlo, g_DTlo);

    cudaFuncSetAttribute(mgemm<EPI_ELU1,true>,     cudaFuncAttributeMaxDynamicSharedMemorySize, SMEM_DYN);
    cudaFuncSetAttribute(mgemm<EPI_NONE,false>,    cudaFuncAttributeMaxDynamicSharedMemorySize, SMEM_DYN);
    cudaFuncSetAttribute(mgemm<EPI_NONE,true>,     cudaFuncAttributeMaxDynamicSharedMemorySize, SMEM_DYN);
    cudaFuncSetAttribute(mgemm<EPI_ADD,false>,     cudaFuncAttributeMaxDynamicSharedMemorySize, SMEM_DYN);
    cudaFuncSetAttribute(mgemm<EPI_SILU,false>,    cudaFuncAttributeMaxDynamicSharedMemorySize, SMEM_DYN);
    cudaFuncSetAttribute(mgemm<EPI_MUL,true>,      cudaFuncAttributeMaxDynamicSharedMemorySize, SMEM_DYN);
    cudaFuncSetAttribute(mgemm<EPI_SCALEACC,false>,cudaFuncAttributeMaxDynamicSharedMemorySize, SMEM_DYN);

    const long long Z = 0;
    const dim3 tb(32, 8);

    // 1) rms1 + split
    rms_k<<<Tq, 256>>>(hidden, ln1, pXp, pXhi, pXlo);

    // 2) weight transposes + split (to [N,K] bf16 hi/lo)
    tsplit_k<<<dim3(32,32,1), tb>>>(wq, pWqThi, pWqTlo, HIDq, HIDq, Z,Z,Z,Z);
    tsplit_k<<<dim3(32,32,1), tb>>>(wk, pWkThi, pWkTlo, HIDq, HIDq, Z,Z,Z,Z);
    tsplit_k<<<dim3(32,32,1), tb>>>(wv, pWvThi, pWvTlo, HIDq, HIDq, Z,Z,Z,Z);
    tsplit_k<<<dim3(32,32,1), tb>>>(wo, pWoThi, pWoTlo, HIDq, HIDq, Z,Z,Z,Z);
    tsplit_k<<<dim3(64,32,4), tb>>>(gw, pGThi, pGTlo, IMq, HIDq, Z,(long long)HIDq*IMq, Z,(long long)IMq*HIDq);
    tsplit_k<<<dim3(64,32,4), tb>>>(uw, pUThi, pUTlo, IMq, HIDq, Z,(long long)HIDq*IMq, Z,(long long)IMq*HIDq);
    tsplit_k<<<dim3(32,64,4), tb>>>(dwn, pDThi, pDTlo, HIDq, IMq, Z,(long long)IMq*HIDq, Z,(long long)HIDq*IMq);

    // 3) QKV projections
    dim3 gQKV(HIDq/128, Tq/128, 1);
    mgemm<EPI_ELU1,true><<<gQKV, 256, SMEM_DYN>>>(HIDq,
        pXhi, pXlo, HIDq, Z,Z, pWqThi, pWqTlo, HIDq, Z,Z,
        nullptr, pQhi, pQlo, HIDq, Z,Z, nullptr, nullptr, 0);
    mgemm<EPI_ELU1,true><<<gQKV, 256, SMEM_DYN>>>(HIDq,
        pXhi, pXlo, HIDq, Z,Z, pWkThi, pWkTlo, HIDq, Z,Z,
        nullptr, pKhi, pKlo, HIDq, Z,Z, nullptr, nullptr, 0);
    mgemm<EPI_NONE,false><<<gQKV, 256, SMEM_DYN>>>(HIDq,
        pXhi, pXlo, HIDq, Z,Z, pWvThi, pWvTlo, HIDq, Z,Z,
        pVf, nullptr, nullptr, HIDq, Z,Z, nullptr, nullptr, 0);

    // 4) V transpose per (b,h): [2048 x 256] -> [256 x 2048] bf16 hi/lo
    tsplit_k<<<dim3(8,64,16), tb>>>(pVf, pVthi, pVtlo, HIDq, Sq,
        (long long)Sq*HIDq, (long long)Dq,
        (long long)NHq*Dq*Sq, (long long)Dq*Sq);

    // 5) scores = Q @ K^T per head
    mgemm<EPI_NONE,false><<<dim3(16,16,16), 256, SMEM_DYN>>>(Dq,
        pQhi, pQlo, HIDq, (long long)Sq*HIDq, (long long)Dq,
        pKhi, pKlo, HIDq, (long long)Sq*HIDq, (long long)Dq,
        pS, nullptr, nullptr, Sq, (long long)NHq*Sq*Sq, (long long)Sq*Sq,
        nullptr, nullptr, 0);

    // 6) softmax + split
    softmax_k<<<Bq*NHq*Sq, 256>>>(pS, pPhi, pPlo);

    // 7) O = P @ V per head (split output)
    mgemm<EPI_NONE,true><<<dim3(2,16,16), 256, SMEM_DYN>>>(Sq,
        pPhi, pPlo, Sq, (long long)NHq*Sq*Sq, (long long)Sq*Sq,
        pVthi, pVtlo, Sq, (long long)NHq*Dq*Sq, (long long)Dq*Sq,
        nullptr, pOhi, pOlo, HIDq, (long long)Sq*HIDq, (long long)Dq,
        nullptr, nullptr, 0);

    // 8) h1 = hidden + O @ wo
    mgemm<EPI_ADD,false><<<gQKV, 256, SMEM_DYN>>>(HIDq,
        pOhi, pOlo, HIDq, Z,Z, pWoThi, pWoTlo, HIDq, Z,Z,
        pH1, nullptr, nullptr, HIDq, Z,Z, hidden, nullptr, 0);

    // 9) rms2 + split, router, balance
    rms_k<<<Tq, 256>>>(pH1, ln2, pXp, pX2hi, pX2lo);
    router_k<<<Tq/8, 256>>>(pXp, rwt, rb, pRW);
    balance_k<<<1, 1024>>>(pRW, out, (long long)Tq*HIDq, (long long)out_size);

    // 10) out = h1, then MoE accumulation
    cudaMemcpyAsync(out, pH1, (size_t)Tq*HIDq*sizeof(float), cudaMemcpyDeviceToDevice);

    dim3 gGU(IMq/128, Tq/128, 1);
    dim3 gDN(HIDq/128, Tq/128, 1);
    for (int e = 0; e < Eq; e++) {
        bf16* gt = pGThi + (long long)e*IMq*HIDq;  bf16* gtl = pGTlo + (long long)e*IMq*HIDq;
        bf16* ut = pUThi + (long long)e*IMq*HIDq;  bf16* utl = pUTlo + (long long)e*IMq*HIDq;
        bf16* dt = pDThi + (long long)e*HIDq*IMq;  bf16* dtl = pDTlo + (long long)e*HIDq*IMq;
        mgemm<EPI_SILU,false><<<gGU, 256, SMEM_DYN>>>(HIDq,
            pX2hi, pX2lo, HIDq, Z,Z, gt, gtl, HIDq, Z,Z,
            pG, nullptr, nullptr, IMq, Z,Z, nullptr, nullptr, 0);
        mgemm<EPI_MUL,true><<<gGU, 256, SMEM_DYN>>>(HIDq,
            pX2hi, pX2lo, HIDq, Z,Z, ut, utl, HIDq, Z,Z,
            nullptr, pGUhi, pGUlo, IMq, Z,Z, pG, nullptr, 0);
        mgemm<EPI_SCALEACC,false><<<gDN, 256, SMEM_DYN>>>(IMq,
            pGUhi, pGUlo, IMq, Z,Z, dt, dtl, IMq, Z,Z,
            out, nullptr, nullptr, HIDq, Z,Z, nullptr, pRW + e, Eq);
    }
}

// round 6
// speedup vs baseline: 3.2952x; 1.2321x over previous
#include <cuda_runtime.h>
#include <cuda_fp16.h>
#include <math.h>
#include <stdint.h>

#define Bq 4
#define Sq 2048
#define HIDq 1024
#define NHq 4
#define Dq 256
#define IMq 2048
#define Eq 4
#define Tq (Bq*Sq)

typedef __half h16;

// ---------------- scratch ----------------
__device__ h16 g_Xhi[Tq*HIDq], g_Xlo[Tq*HIDq];
__device__ h16 g_Qhi[Tq*HIDq], g_Qlo[Tq*HIDq];
__device__ h16 g_Khi[Tq*HIDq], g_Klo[Tq*HIDq];
__device__ float g_Vf[Tq*HIDq];
__device__ h16 g_Vthi[HIDq*Tq], g_Vtlo[HIDq*Tq];
__device__ float g_S[67108864];
__device__ h16 g_Phi[67108864], g_Plo[67108864];
__device__ h16 g_Ohi[Tq*HIDq], g_Olo[Tq*HIDq];
__device__ float g_H1[Tq*HIDq], g_Xp[Tq*HIDq];
__device__ h16 g_X2hi[Tq*HIDq], g_X2lo[Tq*HIDq];
__device__ float g_G[Tq*IMq];
__device__ h16 g_GUhi[Tq*IMq], g_GUlo[Tq*IMq];
__device__ float g_RW[Tq*Eq];
__device__ h16 g_WqThi[HIDq*HIDq], g_WqTlo[HIDq*HIDq];
__device__ h16 g_WkThi[HIDq*HIDq], g_WkTlo[HIDq*HIDq];
__device__ h16 g_WvThi[HIDq*HIDq], g_WvTlo[HIDq*HIDq];
__device__ h16 g_WoThi[HIDq*HIDq], g_WoTlo[HIDq*HIDq];
__device__ h16 g_GThi[Eq*IMq*HIDq], g_GTlo[Eq*IMq*HIDq];
__device__ h16 g_UThi[Eq*IMq*HIDq], g_UTlo[Eq*IMq*HIDq];
__device__ h16 g_DThi[Eq*HIDq*IMq], g_DTlo[Eq*HIDq*IMq];

// ---------------- helpers ----------------
__device__ __forceinline__ uint32_t smem_u32(const void* p) {
    uint32_t a;
    asm("{ .reg .u64 t; cvta.to.shared.u64 t, %1; cvt.u32.u64 %0, t; }" : "=r"(a) : "l"(p));
    return a;
}
__device__ __forceinline__ void hsplit(float v, h16& h, h16& l) {
    h = __float2half(v);
    l = __float2half(v - __half2float(h));
}
#define MMAH(c, a0,a1,a2,a3, b0,b1) \
    asm volatile("mma.sync.aligned.m16n8k16.row.col.f32.f16.f16.f32 " \
        "{%0,%1,%2,%3}, {%4,%5,%6,%7}, {%8,%9}, {%0,%1,%2,%3};" \
        : "+f"((c)[0]), "+f"((c)[1]), "+f"((c)[2]), "+f"((c)[3]) \
        : "r"(a0), "r"(a1), "r"(a2), "r"(a3), "r"(b0), "r"(b1))
#define LDSM4(r0,r1,r2,r3, addr) \
    asm volatile("ldmatrix.sync.aligned.m8n8.x4.shared.b16 {%0,%1,%2,%3}, [%4];" \
        : "=r"(r0), "=r"(r1), "=r"(r2), "=r"(r3) : "r"(addr))
#define LDSM2(r0,r1, addr) \
    asm volatile("ldmatrix.sync.aligned.m8n8.x2.shared.b16 {%0,%1}, [%2];" \
        : "=r"(r0), "=r"(r1) : "r"(addr))
#define CPA16(s, g) asm volatile("cp.async.cg.shared.global [%0], [%1], 16;" :: "r"(s), "l"(g))
#define CPA_COMMIT() asm volatile("cp.async.commit_group;")

// ---------------- fp16 split mma.sync GEMM: 128x128 tile, ktile 32 ----------------
// A: [M,K] row-major h16 hi/lo.  B: [N,K] row-major h16 hi(/lo if TERMS==3).
// TERMS=2: Ah*Bh + Al*Bh.  TERMS=3: Ah*Bh + Ah*Bl + Al*Bh.
enum { EPI_NONE = 0, EPI_ELU1, EPI_SILU, EPI_MUL, EPI_ADD, EPI_SCALEACC };
#define TILE_B 10240

template<int EPI, bool SPLIT, int TERMS>
__global__ __launch_bounds__(256, 2)
void mgemm(int K,
           const h16* __restrict__ Ahi, const h16* __restrict__ Alo,
           int lda, long long sAb, long long sAh,
           const h16* __restrict__ Bhi, const h16* __restrict__ Blo,
           int ldb, long long sBb, long long sBh,
           float* C, h16* Chi, h16* Clo,
           int ldc, long long sCb, long long sCh,
           const float* __restrict__ Dp,
           const float* __restrict__ scale, int sstride) {
    constexpr int STAGES = (TERMS == 2) ? 3 : 2;
    constexpr int NTILES = TERMS + 1;           // Ah, Al, Bh (+Bl)
    constexpr int STAGE_BYTES = NTILES * TILE_B;

    extern __shared__ char smc[];
    const int t = threadIdx.x;
    const int lane = t & 31, wid = t >> 5;
    const int wm = wid & 1, wn = wid >> 1;      // warp tile: 64(M) x 32(N)
    const int zb = blockIdx.z >> 2, zh = blockIdx.z & 3;
    const int row0 = blockIdx.y * 128, col0 = blockIdx.x * 128;

    Ahi += (long long)zb * sAb + (long long)zh * sAh;
    Alo += (long long)zb * sAb + (long long)zh * sAh;
    Bhi += (long long)zb * sBb + (long long)zh * sBh;
    if (TERMS == 3) Blo += (long long)zb * sBb + (long long)zh * sBh;
    const long long coff = (long long)zb * sCb + (long long)zh * sCh;

    float c[4][4][4];
    #pragma unroll
    for (int i = 0; i < 4; i++)
        #pragma unroll
        for (int j = 0; j < 4; j++)
            #pragma unroll
            for (int k = 0; k < 4; k++) c[i][j][k] = 0.f;

    const int nkt = K >> 5;
    const uint32_t smu = smem_u32(smc);

    auto stage = [&](int kt, int buf) {
        const int k0 = kt << 5;
        const uint32_t sb = smu + buf * STAGE_BYTES;
        #pragma unroll
        for (int i = 0; i < NTILES * 2; i++) {
            int chunk = t + (i << 8);
            int tile = chunk >> 9;
            int idx = chunk & 511;
            int row = idx >> 2;
            int q = idx & 3;           // 16B = 8 h16
            const h16* g;
            if (tile == 0)      g = Ahi + (long long)(row0 + row) * lda + k0 + q * 8;
            else if (tile == 1) g = Alo + (long long)(row0 + row) * lda + k0 + q * 8;
            else if (tile == 2) g = Bhi + (long long)(col0 + row) * ldb + k0 + q * 8;
            else                g = Blo + (long long)(col0 + row) * ldb + k0 + q * 8;
            CPA16(sb + tile * TILE_B + row * 80 + q * 16, g);
        }
        CPA_COMMIT();
    };

    stage(0, 0);
    if (STAGES == 3) stage(1, 1);

    for (int kt = 0; kt < nkt; kt++) {
        if (kt + STAGES - 1 < nkt) {
            stage(kt + STAGES - 1, (kt + STAGES - 1) % STAGES);
            asm volatile("cp.async.wait_group %0;" :: "n"(STAGES - 1));
        } else {
            const int rem = nkt - 1 - kt;
            if (rem >= 1) asm volatile("cp.async.wait_group 1;");
            else          asm volatile("cp.async.wait_group 0;");
        }
        __syncthreads();
        const uint32_t sb  = smu + (kt % STAGES) * STAGE_BYTES;
        const uint32_t sAh = sb;
        const uint32_t sAl = sb + TILE_B;
        const uint32_t sBh = sb + 2 * TILE_B;
        const uint32_t sBl = sb + 3 * TILE_B;

        #pragma unroll
        for (int k16 = 0; k16 < 2; k16++) {
            const int kc = k16 << 4;
            uint32_t bh[4][2], bl[4][2];
            const uint32_t boff = (uint32_t)(wn * 32 + (lane & 7)) * 80
                                + (uint32_t)(kc + ((lane & 8) ? 8 : 0)) * 2;
            #pragma unroll
            for (int nt = 0; nt < 4; nt++) {
                LDSM2(bh[nt][0], bh[nt][1], sBh + boff + nt * 8 * 80);
                if (TERMS == 3) LDSM2(bl[nt][0], bl[nt][1], sBl + boff + nt * 8 * 80);
            }
            const uint32_t aoff = (uint32_t)(wm * 64 + (lane & 15)) * 80
                                + (uint32_t)(kc + ((lane >> 4) << 3)) * 2;
            #pragma unroll
            for (int mt = 0; mt < 4; mt++) {
                uint32_t ah0, ah1, ah2, ah3, al0, al1, al2, al3;
                LDSM4(ah0, ah1, ah2, ah3, sAh + aoff + mt * 16 * 80);
                LDSM4(al0, al1, al2, al3, sAl + aoff + mt * 16 * 80);
                #pragma unroll
                for (int nt = 0; nt < 4; nt++) {
                    MMAH(c[mt][nt], ah0, ah1, ah2, ah3, bh[nt][0], bh[nt][1]);
                    if (TERMS == 3)
                        MMAH(c[mt][nt], ah0, ah1, ah2, ah3, bl[nt][0], bl[nt][1]);
                    MMAH(c[mt][nt], al0, al1, al2, al3, bh[nt][0], bh[nt][1]);
                }
            }
        }
        __syncthreads();
    }

    // ---------------- epilogue ----------------
    #pragma unroll
    for (int mt = 0; mt < 4; mt++) {
        #pragma unroll
        for (int half = 0; half < 2; half++) {
            const long long r = row0 + wm * 64 + mt * 16 + (lane >> 2) + half * 8;
            float sc = 0.f;
            if (EPI == EPI_SCALEACC) sc = __ldg(scale + r * sstride);
            #pragma unroll
            for (int nt = 0; nt < 4; nt++) {
                const long long gi = r * ldc + col0 + wn * 32 + nt * 8 + (lane & 3) * 2;
                float v0 = c[mt][nt][half * 2 + 0];
                float v1 = c[mt][nt][half * 2 + 1];
                if (EPI == EPI_ELU1) {
                    v0 = (v0 >= 0.f) ? v0 + 1.f : expf(v0);
                    v1 = (v1 >= 0.f) ? v1 + 1.f : expf(v1);
                } else if (EPI == EPI_SILU) {
                    v0 = v0 / (1.f + expf(-v0));
                    v1 = v1 / (1.f + expf(-v1));
                } else if (EPI == EPI_MUL) {
                    float2 d = *(const float2*)(Dp + gi);
                    v0 *= d.x; v1 *= d.y;
                } else if (EPI == EPI_ADD) {
                    float2 d = *(const float2*)(Dp + gi);
                    v0 += d.x; v1 += d.y;
                } else if (EPI == EPI_SCALEACC) {
                    float2 cc = *(const float2*)(C + coff + gi);
                    v0 = fmaf(v0, sc, cc.x); v1 = fmaf(v1, sc, cc.y);
                }
                if (SPLIT) {
                    h16 h0, l0, h1, l1;
                    hsplit(v0, h0, l0); hsplit(v1, h1, l1);
                    __half2 hp; hp.x = h0; hp.y = h1;
                    __half2 lp; lp.x = l0; lp.y = l1;
                    *(__half2*)(Chi + coff + gi) = hp;
                    *(__half2*)(Clo + coff + gi) = lp;
                } else {
                    *(float2*)(C + coff + gi) = make_float2(v0, v1);
                }
            }
        }
    }
}

// ---------------- reductions ----------------
__device__ __forceinline__ float blk_sum(float v, float* sh) {
    __syncthreads();
    int t = threadIdx.x, lane = t & 31, w = t >> 5;
    #pragma unroll
    for (int o = 16; o; o >>= 1) v += __shfl_down_sync(0xffffffffu, v, o);
    if (lane == 0) sh[w] = v;
    __syncthreads();
    float r = (t < (int)(blockDim.x >> 5)) ? sh[t] : 0.f;
    if (w == 0) {
        #pragma unroll
        for (int o = 16; o; o >>= 1) r += __shfl_down_sync(0xffffffffu, r, o);
        if (t == 0) sh[0] = r;
    }
    __syncthreads();
    return sh[0];
}
__device__ __forceinline__ float blk_max(float v, float* sh) {
    __syncthreads();
    int t = threadIdx.x, lane = t & 31, w = t >> 5;
    #pragma unroll
    for (int o = 16; o; o >>= 1) v = fmaxf(v, __shfl_down_sync(0xffffffffu, v, o));
    if (lane == 0) sh[w] = v;
    __syncthreads();
    float r = (t < (int)(blockDim.x >> 5)) ? sh[t] : -1e30f;
    if (w == 0) {
        #pragma unroll
        for (int o = 16; o; o >>= 1) r = fmaxf(r, __shfl_down_sync(0xffffffffu, r, o));
        if (t == 0) sh[0] = r;
    }
    __syncthreads();
    return sh[0];
}

// ---------------- RMSNorm + fp16 split ----------------
__global__ void rms_k(const float* __restrict__ x, const float* __restrict__ w,
                      float* __restrict__ y, h16* __restrict__ yhi, h16* __restrict__ ylo) {
    __shared__ float sh[32];
    long long row = blockIdx.x;
    const float4 xv = *(const float4*)(x + row * HIDq + threadIdx.x * 4);
    float ss = xv.x*xv.x + xv.y*xv.y + xv.z*xv.z + xv.w*xv.w;
    ss = blk_sum(ss, sh);
    float inv = rsqrtf(ss * (1.0f / HIDq) + 1e-6f);
    const float4 wv = *(const float4*)(w + threadIdx.x * 4);
    float v[4] = { xv.x*inv*wv.x, xv.y*inv*wv.y, xv.z*inv*wv.z, xv.w*inv*wv.w };
    float4 p;
    h16 hb[4], lb[4];
    #pragma unroll
    for (int i = 0; i < 4; i++) {
        ((float*)&p)[i] = v[i];
        hsplit(v[i], hb[i], lb[i]);
    }
    *(float4*)(y + row * HIDq + threadIdx.x * 4) = p;
    *(uint2*)(yhi + row * HIDq + threadIdx.x * 4) = *(uint2*)hb;
    *(uint2*)(ylo + row * HIDq + threadIdx.x * 4) = *(uint2*)lb;
}

// ---------------- softmax + fp16 split ----------------
__global__ void softmax_k(const float* __restrict__ s,
                          h16* __restrict__ phi, h16* __restrict__ plo) {
    __shared__ float sh[32];
    long long base = (long long)blockIdx.x * Sq;
    int t = threadIdx.x;
    float v[8]; float mx = -1e30f;
    #pragma unroll
    for (int i = 0; i < 8; i++) { v[i] = s[base + t + 256*i]; mx = fmaxf(mx, v[i]); }
    mx = blk_max(mx, sh);
    float sum = 0.f;
    #pragma unroll
    for (int i = 0; i < 8; i++) { v[i] = expf(v[i] - mx); sum += v[i]; }
    sum = blk_sum(sum, sh);
    float inv = 1.0f / sum;
    #pragma unroll
    for (int i = 0; i < 8; i++) {
        h16 h, l;
        hsplit(v[i] * inv, h, l);
        phi[base + t + 256*i] = h;
        plo[base + t + 256*i] = l;
    }
}

// ---------------- transpose + fp16 split ----------------
__global__ void tsplit_k(const float* __restrict__ in, h16* __restrict__ ohi,
                         h16* __restrict__ olo, int ldin, int ldout,
                         long long sIb, long long sIh, long long sOb, long long sOh) {
    __shared__ float tile[32][33];
    int z = blockIdx.z, zb = z >> 2, zh = z & 3;
    in  += (long long)zb * sIb + (long long)zh * sIh;
    ohi += (long long)zb * sOb + (long long)zh * sOh;
    olo += (long long)zb * sOb + (long long)zh * sOh;
    int r0 = blockIdx.y * 32, c0 = blockIdx.x * 32;
    int tx = threadIdx.x, ty = threadIdx.y;
    #pragma unroll
    for (int k = 0; k < 4; k++)
        tile[ty + 8*k][tx] = in[(long long)(r0 + ty + 8*k) * ldin + c0 + tx];
    __syncthreads();
    #pragma unroll
    for (int k = 0; k < 4; k++) {
        float v = tile[tx][ty + 8*k];
        long long oi = (long long)(c0 + ty + 8*k) * ldout + r0 + tx;
        h16 h, l;
        hsplit(v, h, l);
        ohi[oi] = h;
        olo[oi] = l;
    }
}

// ---------------- router ----------------
__global__ void router_k(const float* __restrict__ x2, const float* __restrict__ rwt,
                         const float* __restrict__ rb, float* __restrict__ rw) {
    int warp = threadIdx.x >> 5, lane = threadIdx.x & 31;
    long long token = (long long)blockIdx.x * (blockDim.x >> 5) + warp;
    const float* xr = x2 + token * HIDq;
    float a0=0.f, a1=0.f, a2=0.f, a3=0.f;
    for (int k = lane; k < HIDq; k += 32) {
        float xv = xr[k];
        float4 w4 = *(const float4*)(rwt + (long long)k * Eq);
        a0 = fmaf(xv, w4.x, a0); a1 = fmaf(xv, w4.y, a1);
        a2 = fmaf(xv, w4.z, a2); a3 = fmaf(xv, w4.w, a3);
    }
    #pragma unroll
    for (int o = 16; o; o >>= 1) {
        a0 += __shfl_down_sync(0xffffffffu, a0, o);
        a1 += __shfl_down_sync(0xffffffffu, a1, o);
        a2 += __shfl_down_sync(0xffffffffu, a2, o);
        a3 += __shfl_down_sync(0xffffffffu, a3, o);
    }
    if (lane == 0) {
        float l0=a0+rb[0], l1=a1+rb[1], l2=a2+rb[2], l3=a3+rb[3];
        float m = fmaxf(fmaxf(l0,l1), fmaxf(l2,l3));
        float e0=expf(l0-m), e1=expf(l1-m), e2=expf(l2-m), e3=expf(l3-m);
        float inv = 1.0f / (e0+e1+e2+e3);
        float4 o4; o4.x=e0*inv; o4.y=e1*inv; o4.z=e2*inv; o4.w=e3*inv;
        *(float4*)(rw + token * Eq) = o4;
    }
}

// ---------------- balance loss ----------------
__global__ void balance_k(const float* __restrict__ rw, float* __restrict__ out,
                          long long tail_begin, long long out_size) {
    __shared__ float red[1024];
    int t = threadIdx.x;
    float s = 0.f;
    for (int idx = t; idx < Sq * Eq; idx += 1024) {
        int srow = idx / Eq, e = idx % Eq;
        float m = 0.f;
        #pragma unroll
        for (int b = 0; b < Bq; b++) m += rw[((long long)b * Sq + srow) * Eq + e];
        m *= (1.0f / Bq);
        float d = m - 1.0f / Eq;
        s += d * d;
    }
    red[t] = s;
    __syncthreads();
    for (int o = 512; o; o >>= 1) { if (t < o) red[t] += red[t + o]; __syncthreads(); }
    if (t == 0) {
        float loss = red[0] / ((float)Sq * Eq) * 0.01f;
        for (long long i = tail_begin; i < out_size; i++) out[i] = loss;
    }
}

// ---------------- host ----------------
#define SYMF(p, s) float* p; cudaGetSymbolAddress((void**)&p, s)
#define SYMH(p, s) h16* p; cudaGetSymbolAddress((void**)&p, s)
#define SMEM2 (3*3*TILE_B)
#define SMEM3 (2*4*TILE_B)

extern "C" void kernel_launch(void* const* d_in, const int* in_sizes, int n_in,
                              void* d_out, int out_size) {
    const float* hidden = (const float*)d_in[0];
    const float* ln1 = (const float*)d_in[1];
    const float* wq = (const float*)d_in[2];
    const float* wk = (const float*)d_in[3];
    const float* wv = (const float*)d_in[4];
    const float* wo = (const float*)d_in[5];
    const float* ln2 = (const float*)d_in[6];
    const float* rwt = (const float*)d_in[7];
    const float* rb = (const float*)d_in[8];
    const float* gw = (const float*)d_in[9];
    const float* uw = (const float*)d_in[10];
    const float* dwn = (const float*)d_in[11];
    float* out = (float*)d_out;

    SYMH(pXhi, g_Xhi); SYMH(pXlo, g_Xlo); SYMH(pQhi, g_Qhi); SYMH(pQlo, g_Qlo);
    SYMH(pKhi, g_Khi); SYMH(pKlo, g_Klo); SYMF(pVf, g_Vf);
    SYMH(pVthi, g_Vthi); SYMH(pVtlo, g_Vtlo);
    SYMF(pS, g_S); SYMH(pPhi, g_Phi); SYMH(pPlo, g_Plo);
    SYMH(pOhi, g_Ohi); SYMH(pOlo, g_Olo); SYMF(pH1, g_H1); SYMF(pXp, g_Xp);
    SYMH(pX2hi, g_X2hi); SYMH(pX2lo, g_X2lo);
    SYMF(pG, g_G); SYMH(pGUhi, g_GUhi); SYMH(pGUlo, g_GUlo); SYMF(pRW, g_RW);
    SYMH(pWqThi, g_WqThi); SYMH(pWqTlo, g_WqTlo);
    SYMH(pWkThi, g_WkThi); SYMH(pWkTlo, g_WkTlo);
    SYMH(pWvThi, g_WvThi); SYMH(pWvTlo, g_WvTlo);
    SYMH(pWoThi, g_WoThi); SYMH(pWoTlo, g_WoTlo);
    SYMH(pGThi, g_GThi); SYMH(pGTlo, g_GTlo);
    SYMH(pUThi, g_UThi); SYMH(pUTlo, g_UTlo);
    SYMH(pDThi, g_DThi); SYMH(pDTlo, g_DTlo);

    cudaFuncSetAttribute(mgemm<EPI_ELU1,true,3>,     cudaFuncAttributeMaxDynamicSharedMemorySize, SMEM3);
    cudaFuncSetAttribute(mgemm<EPI_NONE,false,3>,    cudaFuncAttributeMaxDynamicSharedMemorySize, SMEM3);
    cudaFuncSetAttribute(mgemm<EPI_NONE,false,2>,    cudaFuncAttributeMaxDynamicSharedMemorySize, SMEM2);
    cudaFuncSetAttribute(mgemm<EPI_NONE,true,2>,     cudaFuncAttributeMaxDynamicSharedMemorySize, SMEM2);
    cudaFuncSetAttribute(mgemm<EPI_ADD,false,2>,     cudaFuncAttributeMaxDynamicSharedMemorySize, SMEM2);
    cudaFuncSetAttribute(mgemm<EPI_SILU,false,2>,    cudaFuncAttributeMaxDynamicSharedMemorySize, SMEM2);
    cudaFuncSetAttribute(mgemm<EPI_MUL,true,2>,      cudaFuncAttributeMaxDynamicSharedMemorySize, SMEM2);
    cudaFuncSetAttribute(mgemm<EPI_SCALEACC,false,2>,cudaFuncAttributeMaxDynamicSharedMemorySize, SMEM2);

    const long long Z = 0;
    const dim3 tb(32, 8);

    // 1) rms1 + split
    rms_k<<<Tq, 256>>>(hidden, ln1, pXp, pXhi, pXlo);

    // 2) weight transposes + split (to [N,K] fp16 hi/lo)
    tsplit_k<<<dim3(32,32,1), tb>>>(wq, pWqThi, pWqTlo, HIDq, HIDq, Z,Z,Z,Z);
    tsplit_k<<<dim3(32,32,1), tb>>>(wk, pWkThi, pWkTlo, HIDq, HIDq, Z,Z,Z,Z);
    tsplit_k<<<dim3(32,32,1), tb>>>(wv, pWvThi, pWvTlo, HIDq, HIDq, Z,Z,Z,Z);
    tsplit_k<<<dim3(32,32,1), tb>>>(wo, pWoThi, pWoTlo, HIDq, HIDq, Z,Z,Z,Z);
    tsplit_k<<<dim3(64,32,4), tb>>>(gw, pGThi, pGTlo, IMq, HIDq, Z,(long long)HIDq*IMq, Z,(long long)IMq*HIDq);
    tsplit_k<<<dim3(64,32,4), tb>>>(uw, pUThi, pUTlo, IMq, HIDq, Z,(long long)HIDq*IMq, Z,(long long)IMq*HIDq);
    tsplit_k<<<dim3(32,64,4), tb>>>(dwn, pDThi, pDTlo, HIDq, IMq, Z,(long long)IMq*HIDq, Z,(long long)HIDq*IMq);

    // 3) QKV projections (Q,K 3-term; V 2-term)
    dim3 gQKV(HIDq/128, Tq/128, 1);
    mgemm<EPI_ELU1,true,3><<<gQKV, 256, SMEM3>>>(HIDq,
        pXhi, pXlo, HIDq, Z,Z, pWqThi, pWqTlo, HIDq, Z,Z,
        nullptr, pQhi, pQlo, HIDq, Z,Z, nullptr, nullptr, 0);
    mgemm<EPI_ELU1,true,3><<<gQKV, 256, SMEM3>>>(HIDq,
        pXhi, pXlo, HIDq, Z,Z, pWkThi, pWkTlo, HIDq, Z,Z,
        nullptr, pKhi, pKlo, HIDq, Z,Z, nullptr, nullptr, 0);
    mgemm<EPI_NONE,false,2><<<gQKV, 256, SMEM2>>>(HIDq,
        pXhi, pXlo, HIDq, Z,Z, pWvThi, pWvTlo, HIDq, Z,Z,
        pVf, nullptr, nullptr, HIDq, Z,Z, nullptr, nullptr, 0);

    // 4) V transpose per (b,h): [2048 x 256] -> [256 x 2048] fp16 hi/lo
    tsplit_k<<<dim3(8,64,16), tb>>>(pVf, pVthi, pVtlo, HIDq, Sq,
        (long long)Sq*HIDq, (long long)Dq,
        (long long)NHq*Dq*Sq, (long long)Dq*Sq);

    // 5) scores = Q @ K^T per head (3-term)
    mgemm<EPI_NONE,false,3><<<dim3(16,16,16), 256, SMEM3>>>(Dq,
        pQhi, pQlo, HIDq, (long long)Sq*HIDq, (long long)Dq,
        pKhi, pKlo, HIDq, (long long)Sq*HIDq, (long long)Dq,
        pS, nullptr, nullptr, Sq, (long long)NHq*Sq*Sq, (long long)Sq*Sq,
        nullptr, nullptr, 0);

    // 6) softmax + split
    softmax_k<<<Bq*NHq*Sq, 256>>>(pS, pPhi, pPlo);

    // 7) O = P @ V per head (2-term, split output)
    mgemm<EPI_NONE,true,2><<<dim3(2,16,16), 256, SMEM2>>>(Sq,
        pPhi, pPlo, Sq, (long long)NHq*Sq*Sq, (long long)Sq*Sq,
        pVthi, pVtlo, Sq, (long long)NHq*Dq*Sq, (long long)Dq*Sq,
        nullptr, pOhi, pOlo, HIDq, (long long)Sq*HIDq, (long long)Dq,
        nullptr, nullptr, 0);

    // 8) h1 = hidden + O @ wo (2-term)
    mgemm<EPI_ADD,false,2><<<gQKV, 256, SMEM2>>>(HIDq,
        pOhi, pOlo, HIDq, Z,Z, pWoThi, pWoTlo, HIDq, Z,Z,
        pH1, nullptr, nullptr, HIDq, Z,Z, hidden, nullptr, 0);

    // 9) rms2 + split, router, balance
    rms_k<<<Tq, 256>>>(pH1, ln2, pXp, pX2hi, pX2lo);
    router_k<<<Tq/8, 256>>>(pXp, rwt, rb, pRW);
    balance_k<<<1, 1024>>>(pRW, out, (long long)Tq*HIDq, (long long)out_size);

    // 10) out = h1, then MoE accumulation (all 2-term)
    cudaMemcpyAsync(out, pH1, (size_t)Tq*HIDq*sizeof(float), cudaMemcpyDeviceToDevice);

    dim3 gGU(IMq/128, Tq/128, 1);
    dim3 gDN(HIDq/128, Tq/128, 1);
    for (int e = 0; e < Eq; e++) {
        h16* gt = pGThi + (long long)e*IMq*HIDq;  h16* gtl = pGTlo + (long long)e*IMq*HIDq;
        h16* ut = pUThi + (long long)e*IMq*HIDq;  h16* utl = pUTlo + (long long)e*IMq*HIDq;
        h16* dt = pDThi + (long long)e*HIDq*IMq;  h16* dtl = pDTlo + (long long)e*HIDq*IMq;
        mgemm<EPI_SILU,false,2><<<gGU, 256, SMEM2>>>(HIDq,
            pX2hi, pX2lo, HIDq, Z,Z, gt, gtl, HIDq, Z,Z,
            pG, nullptr, nullptr, IMq, Z,Z, nullptr, nullptr, 0);
        mgemm<EPI_MUL,true,2><<<gGU, 256, SMEM2>>>(HIDq,
            pX2hi, pX2lo, HIDq, Z,Z, ut, utl, HIDq, Z,Z,
            nullptr, pGUhi, pGUlo, IMq, Z,Z, pG, nullptr, 0);
        mgemm<EPI_SCALEACC,false,2><<<gDN, 256, SMEM2>>>(IMq,
            pGUhi, pGUlo, IMq, Z,Z, dt, dtl, IMq, Z,Z,
            out, nullptr, nullptr, HIDq, Z,Z, nullptr, pRW + e, Eq);
    }
}

// round 7
// speedup vs baseline: 4.8396x; 1.4687x over previous
#include <cuda_runtime.h>
#include <cuda_fp16.h>
#include <math.h>
#include <stdint.h>

#define Bq 4
#define Sq 2048
#define HIDq 1024
#define NHq 4
#define Dq 256
#define IMq 2048
#define Eq 4
#define Tq (Bq*Sq)

typedef __half h16;

// ---------------- scratch ----------------
__device__ h16 g_Xhi[Tq*HIDq], g_Xlo[Tq*HIDq];
__device__ h16 g_Qhi[Tq*HIDq], g_Qlo[Tq*HIDq];
__device__ h16 g_Khi[Tq*HIDq], g_Klo[Tq*HIDq];
__device__ float g_Vf[Tq*HIDq];
__device__ h16 g_Vthi[HIDq*Tq], g_Vtlo[HIDq*Tq];
__device__ float g_S[67108864];
__device__ h16 g_Phi[67108864];
__device__ h16 g_Ohi[Tq*HIDq];
__device__ float g_H1[Tq*HIDq], g_Xp[Tq*HIDq];
__device__ h16 g_X2hi[Tq*HIDq], g_X2lo[Tq*HIDq];
__device__ float g_G[Tq*IMq];
__device__ h16 g_GUhi[Tq*IMq];
__device__ float g_RW[Tq*Eq];
__device__ h16 g_WqThi[HIDq*HIDq], g_WqTlo[HIDq*HIDq];
__device__ h16 g_WkThi[HIDq*HIDq], g_WkTlo[HIDq*HIDq];
__device__ h16 g_WvThi[HIDq*HIDq], g_WvTlo[HIDq*HIDq];
__device__ h16 g_WoThi[HIDq*HIDq], g_WoTlo[HIDq*HIDq];
__device__ h16 g_GThi[Eq*IMq*HIDq], g_GTlo[Eq*IMq*HIDq];
__device__ h16 g_UThi[Eq*IMq*HIDq], g_UTlo[Eq*IMq*HIDq];
__device__ h16 g_DThi[Eq*HIDq*IMq], g_DTlo[Eq*HIDq*IMq];

// ---------------- helpers ----------------
__device__ __forceinline__ uint32_t smem_u32(const void* p) {
    uint32_t a;
    asm("{ .reg .u64 t; cvta.to.shared.u64 t, %1; cvt.u32.u64 %0, t; }" : "=r"(a) : "l"(p));
    return a;
}
__device__ __forceinline__ void hsplit(float v, h16& h, h16& l) {
    h = __float2half(v);
    l = __float2half(v - __half2float(h));
}
#define MMAH(c, a0,a1,a2,a3, b0,b1) \
    asm volatile("mma.sync.aligned.m16n8k16.row.col.f32.f16.f16.f32 " \
        "{%0,%1,%2,%3}, {%4,%5,%6,%7}, {%8,%9}, {%0,%1,%2,%3};" \
        : "+f"((c)[0]), "+f"((c)[1]), "+f"((c)[2]), "+f"((c)[3]) \
        : "r"(a0), "r"(a1), "r"(a2), "r"(a3), "r"(b0), "r"(b1))
#define LDSM4(r0,r1,r2,r3, addr) \
    asm volatile("ldmatrix.sync.aligned.m8n8.x4.shared.b16 {%0,%1,%2,%3}, [%4];" \
        : "=r"(r0), "=r"(r1), "=r"(r2), "=r"(r3) : "r"(addr))
#define LDSM2(r0,r1, addr) \
    asm volatile("ldmatrix.sync.aligned.m8n8.x2.shared.b16 {%0,%1}, [%2];" \
        : "=r"(r0), "=r"(r1) : "r"(addr))
#define CPA16(s, g) asm volatile("cp.async.cg.shared.global [%0], [%1], 16;" :: "r"(s), "l"(g))
#define CPA_COMMIT() asm volatile("cp.async.commit_group;")

// ---------------- fp16 split mma.sync GEMM: 128x128 tile, ktile 32 ----------------
// A: [M,K] row-major h16.  B: [N,K] row-major h16.
// TERMS=1: Ah*Bh.   TERMS=3: Ah*Bh + Ah*Bl + Al*Bh.
// SPLIT: 0 = fp32 C, 1 = h16 hi only, 2 = h16 hi+lo.
enum { EPI_NONE = 0, EPI_ELU1, EPI_SILU, EPI_MUL, EPI_ADD, EPI_SCALEACC };
#define TILE_B 10240
#define SMEM_DYN 81920

template<int EPI, int SPLIT, int TERMS>
__global__ __launch_bounds__(256, 2)
void mgemm(int K,
           const h16* __restrict__ Ahi, const h16* __restrict__ Alo,
           int lda, long long sAb, long long sAh,
           const h16* __restrict__ Bhi, const h16* __restrict__ Blo,
           int ldb, long long sBb, long long sBh,
           float* C, h16* Chi, h16* Clo,
           int ldc, long long sCb, long long sCh,
           const float* __restrict__ Dp,
           const float* __restrict__ scale, int sstride) {
    constexpr int STAGES = (TERMS == 1) ? 4 : 2;
    constexpr int NTILES = (TERMS == 1) ? 2 : 4;
    constexpr int STAGE_BYTES = NTILES * TILE_B;

    extern __shared__ char smc[];
    const int t = threadIdx.x;
    const int lane = t & 31, wid = t >> 5;
    const int wm = wid & 1, wn = wid >> 1;      // warp tile: 64(M) x 32(N)
    const int zb = blockIdx.z >> 2, zh = blockIdx.z & 3;
    const int row0 = blockIdx.y * 128, col0 = blockIdx.x * 128;

    Ahi += (long long)zb * sAb + (long long)zh * sAh;
    Bhi += (long long)zb * sBb + (long long)zh * sBh;
    if (TERMS == 3) {
        Alo += (long long)zb * sAb + (long long)zh * sAh;
        Blo += (long long)zb * sBb + (long long)zh * sBh;
    }
    const long long coff = (long long)zb * sCb + (long long)zh * sCh;

    float c[4][4][4];
    #pragma unroll
    for (int i = 0; i < 4; i++)
        #pragma unroll
        for (int j = 0; j < 4; j++)
            #pragma unroll
            for (int k = 0; k < 4; k++) c[i][j][k] = 0.f;

    const int nkt = K >> 5;
    const uint32_t smu = smem_u32(smc);

    // tile order in smem: 0=Ah, 1=Bh, 2=Al, 3=Bl
    auto stage = [&](int kt, int buf) {
        const int k0 = kt << 5;
        const uint32_t sb = smu + buf * STAGE_BYTES;
        #pragma unroll
        for (int i = 0; i < NTILES * 2; i++) {
            int chunk = t + (i << 8);
            int tile = chunk >> 9;
            int idx = chunk & 511;
            int row = idx >> 2;
            int q = idx & 3;           // 16B = 8 h16
            const h16* g;
            if (tile == 0)      g = Ahi + (long long)(row0 + row) * lda + k0 + q * 8;
            else if (tile == 1) g = Bhi + (long long)(col0 + row) * ldb + k0 + q * 8;
            else if (tile == 2) g = Alo + (long long)(row0 + row) * lda + k0 + q * 8;
            else                g = Blo + (long long)(col0 + row) * ldb + k0 + q * 8;
            CPA16(sb + tile * TILE_B + row * 80 + q * 16, g);
        }
        CPA_COMMIT();
    };

    stage(0, 0);
    #pragma unroll
    for (int s = 1; s < STAGES - 1; s++)
        if (s < nkt) stage(s, s);

    for (int kt = 0; kt < nkt; kt++) {
        if (kt + STAGES - 1 < nkt)
            stage(kt + STAGES - 1, (kt + STAGES - 1) % STAGES);
        int rem = nkt - 1 - kt;
        if (rem > STAGES - 1) rem = STAGES - 1;
        if (rem >= 3)      asm volatile("cp.async.wait_group 3;");
        else if (rem == 2) asm volatile("cp.async.wait_group 2;");
        else if (rem == 1) asm volatile("cp.async.wait_group 1;");
        else               asm volatile("cp.async.wait_group 0;");
        __syncthreads();
        const uint32_t sb  = smu + (kt % STAGES) * STAGE_BYTES;
        const uint32_t sAh = sb;
        const uint32_t sBh = sb + TILE_B;
        const uint32_t sAl = sb + 2 * TILE_B;
        const uint32_t sBl = sb + 3 * TILE_B;

        #pragma unroll
        for (int k16 = 0; k16 < 2; k16++) {
            const int kc = k16 << 4;
            uint32_t bh[4][2], bl[4][2];
            const uint32_t boff = (uint32_t)(wn * 32 + (lane & 7)) * 80
                                + (uint32_t)(kc + ((lane & 8) ? 8 : 0)) * 2;
            #pragma unroll
            for (int nt = 0; nt < 4; nt++) {
                LDSM2(bh[nt][0], bh[nt][1], sBh + boff + nt * 8 * 80);
                if (TERMS == 3) LDSM2(bl[nt][0], bl[nt][1], sBl + boff + nt * 8 * 80);
            }
            const uint32_t aoff = (uint32_t)(wm * 64 + (lane & 15)) * 80
                                + (uint32_t)(kc + ((lane >> 4) << 3)) * 2;
            #pragma unroll
            for (int mt = 0; mt < 4; mt++) {
                uint32_t ah0, ah1, ah2, ah3;
                LDSM4(ah0, ah1, ah2, ah3, sAh + aoff + mt * 16 * 80);
                uint32_t al0, al1, al2, al3;
                if (TERMS == 3) LDSM4(al0, al1, al2, al3, sAl + aoff + mt * 16 * 80);
                #pragma unroll
                for (int nt = 0; nt < 4; nt++) {
                    MMAH(c[mt][nt], ah0, ah1, ah2, ah3, bh[nt][0], bh[nt][1]);
                    if (TERMS == 3) {
                        MMAH(c[mt][nt], ah0, ah1, ah2, ah3, bl[nt][0], bl[nt][1]);
                        MMAH(c[mt][nt], al0, al1, al2, al3, bh[nt][0], bh[nt][1]);
                    }
                }
            }
        }
        __syncthreads();
    }

    // ---------------- epilogue ----------------
    #pragma unroll
    for (int mt = 0; mt < 4; mt++) {
        #pragma unroll
        for (int half = 0; half < 2; half++) {
            const long long r = row0 + wm * 64 + mt * 16 + (lane >> 2) + half * 8;
            float sc = 0.f;
            if (EPI == EPI_SCALEACC) sc = __ldg(scale + r * sstride);
            #pragma unroll
            for (int nt = 0; nt < 4; nt++) {
                const long long gi = r * ldc + col0 + wn * 32 + nt * 8 + (lane & 3) * 2;
                float v0 = c[mt][nt][half * 2 + 0];
                float v1 = c[mt][nt][half * 2 + 1];
                if (EPI == EPI_ELU1) {
                    v0 = (v0 >= 0.f) ? v0 + 1.f : expf(v0);
                    v1 = (v1 >= 0.f) ? v1 + 1.f : expf(v1);
                } else if (EPI == EPI_SILU) {
                    v0 = v0 / (1.f + expf(-v0));
                    v1 = v1 / (1.f + expf(-v1));
                } else if (EPI == EPI_MUL) {
                    float2 d = *(const float2*)(Dp + gi);
                    v0 *= d.x; v1 *= d.y;
                } else if (EPI == EPI_ADD) {
                    float2 d = *(const float2*)(Dp + gi);
                    v0 += d.x; v1 += d.y;
                } else if (EPI == EPI_SCALEACC) {
                    float2 cc = *(const float2*)(C + coff + gi);
                    v0 = fmaf(v0, sc, cc.x); v1 = fmaf(v1, sc, cc.y);
                }
                if (SPLIT == 2) {
                    h16 h0, l0, h1, l1;
                    hsplit(v0, h0, l0); hsplit(v1, h1, l1);
                    __half2 hp; hp.x = h0; hp.y = h1;
                    __half2 lp; lp.x = l0; lp.y = l1;
                    *(__half2*)(Chi + coff + gi) = hp;
                    *(__half2*)(Clo + coff + gi) = lp;
                } else if (SPLIT == 1) {
                    __half2 hp; hp.x = __float2half(v0); hp.y = __float2half(v1);
                    *(__half2*)(Chi + coff + gi) = hp;
                } else {
                    *(float2*)(C + coff + gi) = make_float2(v0, v1);
                }
            }
        }
    }
}

// ---------------- reductions ----------------
__device__ __forceinline__ float blk_sum(float v, float* sh) {
    __syncthreads();
    int t = threadIdx.x, lane = t & 31, w = t >> 5;
    #pragma unroll
    for (int o = 16; o; o >>= 1) v += __shfl_down_sync(0xffffffffu, v, o);
    if (lane == 0) sh[w] = v;
    __syncthreads();
    float r = (t < (int)(blockDim.x >> 5)) ? sh[t] : 0.f;
    if (w == 0) {
        #pragma unroll
        for (int o = 16; o; o >>= 1) r += __shfl_down_sync(0xffffffffu, r, o);
        if (t == 0) sh[0] = r;
    }
    __syncthreads();
    return sh[0];
}
__device__ __forceinline__ float blk_max(float v, float* sh) {
    __syncthreads();
    int t = threadIdx.x, lane = t & 31, w = t >> 5;
    #pragma unroll
    for (int o = 16; o; o >>= 1) v = fmaxf(v, __shfl_down_sync(0xffffffffu, v, o));
    if (lane == 0) sh[w] = v;
    __syncthreads();
    float r = (t < (int)(blockDim.x >> 5)) ? sh[t] : -1e30f;
    if (w == 0) {
        #pragma unroll
        for (int o = 16; o; o >>= 1) r = fmaxf(r, __shfl_down_sync(0xffffffffu, r, o));
        if (t == 0) sh[0] = r;
    }
    __syncthreads();
    return sh[0];
}

// ---------------- RMSNorm + fp16 split ----------------
__global__ void rms_k(const float* __restrict__ x, const float* __restrict__ w,
                      float* __restrict__ y, h16* __restrict__ yhi, h16* __restrict__ ylo) {
    __shared__ float sh[32];
    long long row = blockIdx.x;
    const float4 xv = *(const float4*)(x + row * HIDq + threadIdx.x * 4);
    float ss = xv.x*xv.x + xv.y*xv.y + xv.z*xv.z + xv.w*xv.w;
    ss = blk_sum(ss, sh);
    float inv = rsqrtf(ss * (1.0f / HIDq) + 1e-6f);
    const float4 wv = *(const float4*)(w + threadIdx.x * 4);
    float v[4] = { xv.x*inv*wv.x, xv.y*inv*wv.y, xv.z*inv*wv.z, xv.w*inv*wv.w };
    float4 p;
    h16 hb[4], lb[4];
    #pragma unroll
    for (int i = 0; i < 4; i++) {
        ((float*)&p)[i] = v[i];
        hsplit(v[i], hb[i], lb[i]);
    }
    *(float4*)(y + row * HIDq + threadIdx.x * 4) = p;
    *(uint2*)(yhi + row * HIDq + threadIdx.x * 4) = *(uint2*)hb;
    *(uint2*)(ylo + row * HIDq + threadIdx.x * 4) = *(uint2*)lb;
}

// ---------------- softmax (hi only) ----------------
__global__ void softmax_k(const float* __restrict__ s, h16* __restrict__ phi) {
    __shared__ float sh[32];
    long long base = (long long)blockIdx.x * Sq;
    int t = threadIdx.x;
    float v[8]; float mx = -1e30f;
    #pragma unroll
    for (int i = 0; i < 8; i++) { v[i] = s[base + t + 256*i]; mx = fmaxf(mx, v[i]); }
    mx = blk_max(mx, sh);
    float sum = 0.f;
    #pragma unroll
    for (int i = 0; i < 8; i++) { v[i] = expf(v[i] - mx); sum += v[i]; }
    sum = blk_sum(sum, sh);
    float inv = 1.0f / sum;
    #pragma unroll
    for (int i = 0; i < 8; i++)
        phi[base + t + 256*i] = __float2half(v[i] * inv);
}

// ---------------- transpose + fp16 split ----------------
__global__ void tsplit_k(const float* __restrict__ in, h16* __restrict__ ohi,
                         h16* __restrict__ olo, int ldin, int ldout,
                         long long sIb, long long sIh, long long sOb, long long sOh) {
    __shared__ float tile[32][33];
    int z = blockIdx.z, zb = z >> 2, zh = z & 3;
    in  += (long long)zb * sIb + (long long)zh * sIh;
    ohi += (long long)zb * sOb + (long long)zh * sOh;
    olo += (long long)zb * sOb + (long long)zh * sOh;
    int r0 = blockIdx.y * 32, c0 = blockIdx.x * 32;
    int tx = threadIdx.x, ty = threadIdx.y;
    #pragma unroll
    for (int k = 0; k < 4; k++)
        tile[ty + 8*k][tx] = in[(long long)(r0 + ty + 8*k) * ldin + c0 + tx];
    __syncthreads();
    #pragma unroll
    for (int k = 0; k < 4; k++) {
        float v = tile[tx][ty + 8*k];
        long long oi = (long long)(c0 + ty + 8*k) * ldout + r0 + tx;
        h16 h, l;
        hsplit(v, h, l);
        ohi[oi] = h;
        olo[oi] = l;
    }
}

// ---------------- router ----------------
__global__ void router_k(const float* __restrict__ x2, const float* __restrict__ rwt,
                         const float* __restrict__ rb, float* __restrict__ rw) {
    int warp = threadIdx.x >> 5, lane = threadIdx.x & 31;
    long long token = (long long)blockIdx.x * (blockDim.x >> 5) + warp;
    const float* xr = x2 + token * HIDq;
    float a0=0.f, a1=0.f, a2=0.f, a3=0.f;
    for (int k = lane; k < HIDq; k += 32) {
        float xv = xr[k];
        float4 w4 = *(const float4*)(rwt + (long long)k * Eq);
        a0 = fmaf(xv, w4.x, a0); a1 = fmaf(xv, w4.y, a1);
        a2 = fmaf(xv, w4.z, a2); a3 = fmaf(xv, w4.w, a3);
    }
    #pragma unroll
    for (int o = 16; o; o >>= 1) {
        a0 += __shfl_down_sync(0xffffffffu, a0, o);
        a1 += __shfl_down_sync(0xffffffffu, a1, o);
        a2 += __shfl_down_sync(0xffffffffu, a2, o);
        a3 += __shfl_down_sync(0xffffffffu, a3, o);
    }
    if (lane == 0) {
        float l0=a0+rb[0], l1=a1+rb[1], l2=a2+rb[2], l3=a3+rb[3];
        float m = fmaxf(fmaxf(l0,l1), fmaxf(l2,l3));
        float e0=expf(l0-m), e1=expf(l1-m), e2=expf(l2-m), e3=expf(l3-m);
        float inv = 1.0f / (e0+e1+e2+e3);
        float4 o4; o4.x=e0*inv; o4.y=e1*inv; o4.z=e2*inv; o4.w=e3*inv;
        *(float4*)(rw + token * Eq) = o4;
    }
}

// ---------------- balance loss ----------------
__global__ void balance_k(const float* __restrict__ rw, float* __restrict__ out,
                          long long tail_begin, long long out_size) {
    __shared__ float red[1024];
    int t = threadIdx.x;
    float s = 0.f;
    for (int idx = t; idx < Sq * Eq; idx += 1024) {
        int srow = idx / Eq, e = idx % Eq;
        float m = 0.f;
        #pragma unroll
        for (int b = 0; b < Bq; b++) m += rw[((long long)b * Sq + srow) * Eq + e];
        m *= (1.0f / Bq);
        float d = m - 1.0f / Eq;
        s += d * d;
    }
    red[t] = s;
    __syncthreads();
    for (int o = 512; o; o >>= 1) { if (t < o) red[t] += red[t + o]; __syncthreads(); }
    if (t == 0) {
        float loss = red[0] / ((float)Sq * Eq) * 0.01f;
        for (long long i = tail_begin; i < out_size; i++) out[i] = loss;
    }
}

// ---------------- host ----------------
#define SYMF(p, s) float* p; cudaGetSymbolAddress((void**)&p, s)
#define SYMH(p, s) h16* p; cudaGetSymbolAddress((void**)&p, s)

extern "C" void kernel_launch(void* const* d_in, const int* in_sizes, int n_in,
                              void* d_out, int out_size) {
    const float* hidden = (const float*)d_in[0];
    const float* ln1 = (const float*)d_in[1];
    const float* wq = (const float*)d_in[2];
    const float* wk = (const float*)d_in[3];
    const float* wv = (const float*)d_in[4];
    const float* wo = (const float*)d_in[5];
    const float* ln2 = (const float*)d_in[6];
    const float* rwt = (const float*)d_in[7];
    const float* rb = (const float*)d_in[8];
    const float* gw = (const float*)d_in[9];
    const float* uw = (const float*)d_in[10];
    const float* dwn = (const float*)d_in[11];
    float* out = (float*)d_out;

    SYMH(pXhi, g_Xhi); SYMH(pXlo, g_Xlo); SYMH(pQhi, g_Qhi); SYMH(pQlo, g_Qlo);
    SYMH(pKhi, g_Khi); SYMH(pKlo, g_Klo); SYMF(pVf, g_Vf);
    SYMH(pVthi, g_Vthi); SYMH(pVtlo, g_Vtlo);
    SYMF(pS, g_S); SYMH(pPhi, g_Phi);
    SYMH(pOhi, g_Ohi); SYMF(pH1, g_H1); SYMF(pXp, g_Xp);
    SYMH(pX2hi, g_X2hi); SYMH(pX2lo, g_X2lo);
    SYMF(pG, g_G); SYMH(pGUhi, g_GUhi); SYMF(pRW, g_RW);
    SYMH(pWqThi, g_WqThi); SYMH(pWqTlo, g_WqTlo);
    SYMH(pWkThi, g_WkThi); SYMH(pWkTlo, g_WkTlo);
    SYMH(pWvThi, g_WvThi); SYMH(pWvTlo, g_WvTlo);
    SYMH(pWoThi, g_WoThi); SYMH(pWoTlo, g_WoTlo);
    SYMH(pGThi, g_GThi); SYMH(pGTlo, g_GTlo);
    SYMH(pUThi, g_UThi); SYMH(pUTlo, g_UTlo);
    SYMH(pDThi, g_DThi); SYMH(pDTlo, g_DTlo);

    cudaFuncSetAttribute(mgemm<EPI_ELU1,2,3>,     cudaFuncAttributeMaxDynamicSharedMemorySize, SMEM_DYN);
    cudaFuncSetAttribute(mgemm<EPI_NONE,0,3>,     cudaFuncAttributeMaxDynamicSharedMemorySize, SMEM_DYN);
    cudaFuncSetAttribute(mgemm<EPI_NONE,0,1>,     cudaFuncAttributeMaxDynamicSharedMemorySize, SMEM_DYN);
    cudaFuncSetAttribute(mgemm<EPI_NONE,1,1>,     cudaFuncAttributeMaxDynamicSharedMemorySize, SMEM_DYN);
    cudaFuncSetAttribute(mgemm<EPI_ADD,0,1>,      cudaFuncAttributeMaxDynamicSharedMemorySize, SMEM_DYN);
    cudaFuncSetAttribute(mgemm<EPI_SILU,0,1>,     cudaFuncAttributeMaxDynamicSharedMemorySize, SMEM_DYN);
    cudaFuncSetAttribute(mgemm<EPI_MUL,1,1>,      cudaFuncAttributeMaxDynamicSharedMemorySize, SMEM_DYN);
    cudaFuncSetAttribute(mgemm<EPI_SCALEACC,0,1>, cudaFuncAttributeMaxDynamicSharedMemorySize, SMEM_DYN);

    const long long Z = 0;
    const dim3 tb(32, 8);

    // 1) rms1 + split
    rms_k<<<Tq, 256>>>(hidden, ln1, pXp, pXhi, pXlo);

    // 2) weight transposes + split (to [N,K] fp16 hi/lo)
    tsplit_k<<<dim3(32,32,1), tb>>>(wq, pWqThi, pWqTlo, HIDq, HIDq, Z,Z,Z,Z);
    tsplit_k<<<dim3(32,32,1), tb>>>(wk, pWkThi, pWkTlo, HIDq, HIDq, Z,Z,Z,Z);
    tsplit_k<<<dim3(32,32,1), tb>>>(wv, pWvThi, pWvTlo, HIDq, HIDq, Z,Z,Z,Z);
    tsplit_k<<<dim3(32,32,1), tb>>>(wo, pWoThi, pWoTlo, HIDq, HIDq, Z,Z,Z,Z);
    tsplit_k<<<dim3(64,32,4), tb>>>(gw, pGThi, pGTlo, IMq, HIDq, Z,(long long)HIDq*IMq, Z,(long long)IMq*HIDq);
    tsplit_k<<<dim3(64,32,4), tb>>>(uw, pUThi, pUTlo, IMq, HIDq, Z,(long long)HIDq*IMq, Z,(long long)IMq*HIDq);
    tsplit_k<<<dim3(32,64,4), tb>>>(dwn, pDThi, pDTlo, HIDq, IMq, Z,(long long)IMq*HIDq, Z,(long long)HIDq*IMq);

    // 3) QKV projections (Q,K 3-term; V 1-term)
    dim3 gQKV(HIDq/128, Tq/128, 1);
    mgemm<EPI_ELU1,2,3><<<gQKV, 256, SMEM_DYN>>>(HIDq,
        pXhi, pXlo, HIDq, Z,Z, pWqThi, pWqTlo, HIDq, Z,Z,
        nullptr, pQhi, pQlo, HIDq, Z,Z, nullptr, nullptr, 0);
    mgemm<EPI_ELU1,2,3><<<gQKV, 256, SMEM_DYN>>>(HIDq,
        pXhi, pXlo, HIDq, Z,Z, pWkThi, pWkTlo, HIDq, Z,Z,
        nullptr, pKhi, pKlo, HIDq, Z,Z, nullptr, nullptr, 0);
    mgemm<EPI_NONE,0,1><<<gQKV, 256, SMEM_DYN>>>(HIDq,
        pXhi, nullptr, HIDq, Z,Z, pWvThi, nullptr, HIDq, Z,Z,
        pVf, nullptr, nullptr, HIDq, Z,Z, nullptr, nullptr, 0);

    // 4) V transpose per (b,h): [2048 x 256] -> [256 x 2048] fp16 hi/lo
    tsplit_k<<<dim3(8,64,16), tb>>>(pVf, pVthi, pVtlo, HIDq, Sq,
        (long long)Sq*HIDq, (long long)Dq,
        (long long)NHq*Dq*Sq, (long long)Dq*Sq);

    // 5) scores = Q @ K^T per head (3-term)
    mgemm<EPI_NONE,0,3><<<dim3(16,16,16), 256, SMEM_DYN>>>(Dq,
        pQhi, pQlo, HIDq, (long long)Sq*HIDq, (long long)Dq,
        pKhi, pKlo, HIDq, (long long)Sq*HIDq, (long long)Dq,
        pS, nullptr, nullptr, Sq, (long long)NHq*Sq*Sq, (long long)Sq*Sq,
        nullptr, nullptr, 0);

    // 6) softmax (hi only)
    softmax_k<<<Bq*NHq*Sq, 256>>>(pS, pPhi);

    // 7) O = P @ V per head (1-term, hi output)
    mgemm<EPI_NONE,1,1><<<dim3(2,16,16), 256, SMEM_DYN>>>(Sq,
        pPhi, nullptr, Sq, (long long)NHq*Sq*Sq, (long long)Sq*Sq,
        pVthi, nullptr, Sq, (long long)NHq*Dq*Sq, (long long)Dq*Sq,
        nullptr, pOhi, nullptr, HIDq, (long long)Sq*HIDq, (long long)Dq,
        nullptr, nullptr, 0);

    // 8) h1 = hidden + O @ wo (1-term)
    mgemm<EPI_ADD,0,1><<<gQKV, 256, SMEM_DYN>>>(HIDq,
        pOhi, nullptr, HIDq, Z,Z, pWoThi, nullptr, HIDq, Z,Z,
        pH1, nullptr, nullptr, HIDq, Z,Z, hidden, nullptr, 0);

    // 9) rms2 + split, router, balance
    rms_k<<<Tq, 256>>>(pH1, ln2, pXp, pX2hi, pX2lo);
    router_k<<<Tq/8, 256>>>(pXp, rwt, rb, pRW);
    balance_k<<<1, 1024>>>(pRW, out, (long long)Tq*HIDq, (long long)out_size);

    // 10) out = h1, then MoE accumulation (all 1-term)
    cudaMemcpyAsync(out, pH1, (size_t)Tq*HIDq*sizeof(float), cudaMemcpyDeviceToDevice);

    dim3 gGU(IMq/128, Tq/128, 1);
    dim3 gDN(HIDq/128, Tq/128, 1);
    for (int e = 0; e < Eq; e++) {
        h16* gt = pGThi + (long long)e*IMq*HIDq;
        h16* ut = pUThi + (long long)e*IMq*HIDq;
        h16* dt = pDThi + (long long)e*HIDq*IMq;
        mgemm<EPI_SILU,0,1><<<gGU, 256, SMEM_DYN>>>(HIDq,
            pX2hi, nullptr, HIDq, Z,Z, gt, nullptr, HIDq, Z,Z,
            pG, nullptr, nullptr, IMq, Z,Z, nullptr, nullptr, 0);
        mgemm<EPI_MUL,1,1><<<gGU, 256, SMEM_DYN>>>(HIDq,
            pX2hi, nullptr, HIDq, Z,Z, ut, nullptr, HIDq, Z,Z,
            nullptr, pGUhi, nullptr, IMq, Z,Z, pG, nullptr, 0);
        mgemm<EPI_SCALEACC,0,1><<<gDN, 256, SMEM_DYN>>>(IMq,
            pGUhi, nullptr, IMq, Z,Z, dt, nullptr, IMq, Z,Z,
            out, nullptr, nullptr, HIDq, Z,Z, nullptr, pRW + e, Eq);
    }
}